// round 12
// baseline (speedup 1.0000x reference)
#include <cuda_runtime.h>
#include <cuda_bf16.h>
#include <math.h>
#include <cstdint>

// B=16, P=1000, N=1000, E=256, H=16, D=16, HD=256
#define BSZ   16
#define PN    1000
#define MROWS (BSZ * PN)
#define LOG2E 1.4426950408889634f

__device__ __forceinline__ float ex2f(float x) {
    float y; asm("ex2.approx.f32 %0,%1;" : "=f"(y) : "f"(x)); return y;
}
__device__ __forceinline__ float frcp(float x) {
    float y; asm("rcp.approx.f32 %0,%1;" : "=f"(y) : "f"(x)); return y;
}
__device__ __forceinline__ uint32_t smem_u32(const void* p) {
    uint32_t a;
    asm("{ .reg .u64 t; cvta.to.shared.u64 t, %1; cvt.u32.u64 %0, t; }"
        : "=r"(a) : "l"(p));
    return a;
}
__device__ __forceinline__ void ldsm4(uint32_t& r0, uint32_t& r1,
                                      uint32_t& r2, uint32_t& r3, uint32_t a) {
    asm volatile("ldmatrix.sync.aligned.m8n8.x4.shared.b16 {%0,%1,%2,%3},[%4];"
                 : "=r"(r0), "=r"(r1), "=r"(r2), "=r"(r3) : "r"(a));
}
__device__ __forceinline__ void ldsm4t(uint32_t& r0, uint32_t& r1,
                                       uint32_t& r2, uint32_t& r3, uint32_t a) {
    asm volatile("ldmatrix.sync.aligned.m8n8.x4.trans.shared.b16 {%0,%1,%2,%3},[%4];"
                 : "=r"(r0), "=r"(r1), "=r"(r2), "=r"(r3) : "r"(a));
}
__device__ __forceinline__ uint32_t packbf(float hi, float lo) {
    uint32_t r; asm("cvt.rn.bf16x2.f32 %0,%1,%2;" : "=r"(r) : "f"(hi), "f"(lo));
    return r;
}
__device__ __forceinline__ void cpa16(uint32_t dst, const void* src) {
    asm volatile("cp.async.cg.shared.global [%0],[%1],16;"
                 :: "r"(dst), "l"(src) : "memory");
}
__device__ __forceinline__ void cpa16p(uint32_t dst, const void* src, int n) {
    asm volatile("cp.async.cg.shared.global [%0],[%1],16,%2;"
                 :: "r"(dst), "l"(src), "r"(n) : "memory");
}
#define MMA16816(C, A, B0, B1) \
    asm volatile("mma.sync.aligned.m16n8k16.row.col.f32.bf16.bf16.f32 " \
        "{%0,%1,%2,%3},{%4,%5,%6,%7},{%8,%9},{%0,%1,%2,%3};" \
        : "+f"((C)[0]), "+f"((C)[1]), "+f"((C)[2]), "+f"((C)[3]) \
        : "r"((A)[0]), "r"((A)[1]), "r"((A)[2]), "r"((A)[3]), \
          "r"(B0), "r"(B1))
#define CP_COMMIT() asm volatile("cp.async.commit_group;" ::: "memory")
#define CP_WAIT1()  asm volatile("cp.async.wait_group 1;" ::: "memory")
#define CP_WAIT0()  asm volatile("cp.async.wait_group 0;" ::: "memory")

__device__ __forceinline__ void split_store2(__nv_bfloat16* __restrict__ H,
                                             __nv_bfloat16* __restrict__ L,
                                             size_t off, float v0, float v1) {
    __nv_bfloat16 h0 = __float2bfloat16_rn(v0);
    __nv_bfloat16 h1 = __float2bfloat16_rn(v1);
    __nv_bfloat16 l0 = __float2bfloat16_rn(v0 - __bfloat162float(h0));
    __nv_bfloat16 l1 = __float2bfloat16_rn(v1 - __bfloat162float(h1));
    ushort2 hh, ll;
    hh.x = __bfloat16_as_ushort(h0); hh.y = __bfloat16_as_ushort(h1);
    ll.x = __bfloat16_as_ushort(l0); ll.y = __bfloat16_as_ushort(l1);
    *(ushort2*)(H + off) = hh;
    *(ushort2*)(L + off) = ll;
}

// ---------------- scratch ----------------
__device__ float g_ROWSUM[MROWS];
__device__ __nv_bfloat16 g_AH[16 * 1024 * 256];
__device__ __nv_bfloat16 g_AL[16 * 1024 * 256];
__device__ __nv_bfloat16 g_BH[16 * 1024 * 256];
__device__ __nv_bfloat16 g_BL[16 * 1024 * 256];
__device__ __nv_bfloat16 g_QH[16 * 1024 * 256];
__device__ __nv_bfloat16 g_QL[16 * 1024 * 256];
__device__ __nv_bfloat16 g_KVH[16 * 1024 * 512];
__device__ __nv_bfloat16 g_KVL[16 * 1024 * 512];
__device__ __nv_bfloat16 g_LH[16 * 1024 * 256];
__device__ __nv_bfloat16 g_LL[16 * 1024 * 256];
__device__ __nv_bfloat16 g_ATH[16 * 1024 * 256];
__device__ __nv_bfloat16 g_ATL[16 * 1024 * 256];
__device__ __nv_bfloat16 g_WKVTH[512 * 256];
__device__ __nv_bfloat16 g_WKVTL[512 * 256];
__device__ __nv_bfloat16 g_WQTH[256 * 256];
__device__ __nv_bfloat16 g_WQTL[256 * 256];
__device__ __nv_bfloat16 g_WCTH[256 * 256];
__device__ __nv_bfloat16 g_WCTL[256 * 256];

__global__ void prep0_k() {
    int i = blockIdx.x * 256 + threadIdx.x;
    if (i < MROWS) {
        g_ROWSUM[i] = 0.f;
    } else if (i < MROWS + 98304) {
        int j = i - MROWS;
        int z = j / 6144, rem = j % 6144;
        int r = 1000 + (rem >> 8), c = rem & 255;
        size_t off = ((size_t)z * 1024 + r) * 256 + c;
        g_ATH[off] = __ushort_as_bfloat16(0);
        g_ATL[off] = __ushort_as_bfloat16(0);
    }
}

__global__ void tsplit_k(const float* __restrict__ Wk, const float* __restrict__ Wv,
                         const float* __restrict__ Wq, const float* __restrict__ Wc)
{
    int idx = blockIdx.x * 256 + threadIdx.x;
    float v; __nv_bfloat16 *H, *L; int off;
    if (idx < 131072) {
        int n = idx >> 8, k = idx & 255;
        v = (n < 256) ? Wk[k * 256 + n] : Wv[k * 256 + (n - 256)];
        H = g_WKVTH; L = g_WKVTL; off = idx;
    } else if (idx < 196608) {
        int i = idx - 131072;
        int n = i >> 8, k = i & 255;
        v = Wq[k * 256 + n];
        H = g_WQTH; L = g_WQTL; off = i;
    } else {
        int i = idx - 196608;
        int n = i >> 8, k = i & 255;
        v = Wc[k * 256 + n];
        H = g_WCTH; L = g_WCTL; off = i;
    }
    __nv_bfloat16 h = __float2bfloat16_rn(v);
    __nv_bfloat16 l = __float2bfloat16_rn(v - __bfloat162float(h));
    H[off] = h; L[off] = l;
}

__global__ void splitg2_k(const float* __restrict__ nodes, const float* __restrict__ last)
{
    int i = blockIdx.x * 256 + threadIdx.x;
    const float* src = nodes;
    __nv_bfloat16* H = g_BH;
    __nv_bfloat16* L = g_BL;
    if (i >= 1048576) {
        i -= 1048576;
        src = last; H = g_LH; L = g_LL;
    }
    int c4 = i & 63;
    int zr = i >> 6;
    int z = zr >> 10, r = zr & 1023;
    float4 v = make_float4(0.f, 0.f, 0.f, 0.f);
    if (r < 1000)
        v = *(const float4*)(src + ((size_t)z * 1000 + r) * 256 + c4 * 4);
    float xs[4] = {v.x, v.y, v.z, v.w};
    ushort4 hh, ll;
    unsigned short* hp = &hh.x;
    unsigned short* lp = &ll.x;
#pragma unroll
    for (int j = 0; j < 4; ++j) {
        __nv_bfloat16 h = __float2bfloat16_rn(xs[j]);
        float res = xs[j] - __bfloat162float(h);
        __nv_bfloat16 l = __float2bfloat16_rn(res);
        hp[j] = __bfloat16_as_ushort(h);
        lp[j] = __bfloat16_as_ushort(l);
    }
    *(ushort4*)(H + (size_t)zr * 256 + c4 * 4) = hh;
    *(ushort4*)(L + (size_t)zr * 256 + c4 * 4) = ll;
}

// ---------------- merged HMMA GEMM: K=32 double-buffer + term-major MMA order ----------------
#define GP_PAD    40
#define GP_TILE   (128 * GP_PAD)
#define GP_OPB    (GP_TILE * 2)
#define GP_STAGE  (4 * GP_OPB)
#define G3_SMEM   (2 * GP_STAGE)

template <int EPI>
__global__ void __launch_bounds__(256, 2)
mma_gemm(const __nv_bfloat16* __restrict__ AH, const __nv_bfloat16* __restrict__ AL,
         const __nv_bfloat16* __restrict__ BH, const __nv_bfloat16* __restrict__ BL,
         __nv_bfloat16* __restrict__ CH, __nv_bfloat16* __restrict__ CL, int ldc,
         const float* __restrict__ attr, const float* __restrict__ wql,
         const float* __restrict__ bias,
         const float* __restrict__ mask, float* __restrict__ out,
         float* __restrict__ rsum)
{
    extern __shared__ __align__(16) __nv_bfloat16 smb[];

    const int tid = threadIdx.x;
    const int lane = tid & 31;
    const int w = tid >> 5;
    const int wm = w & 3, wn = w >> 2;
    const int z = blockIdx.z, m0 = blockIdx.y * 128, n0 = blockIdx.x * 128;

    const __nv_bfloat16* pAH = AH + ((size_t)z * 1024 + m0) * 256;
    const __nv_bfloat16* pAL = AL + ((size_t)z * 1024 + m0) * 256;
    const size_t boff = (EPI == 3) ? ((size_t)z * 1024 + n0) * 256 : (size_t)n0 * 256;
    const __nv_bfloat16* pBH = BH + boff;
    const __nv_bfloat16* pBL = BL + boff;

    float acc[2][8][4];
#pragma unroll
    for (int mi = 0; mi < 2; ++mi)
#pragma unroll
        for (int ni = 0; ni < 8; ++ni)
#pragma unroll
            for (int q = 0; q < 4; ++q) acc[mi][ni][q] = 0.f;

    const int arow = ((lane >> 3) & 1) * 8 + (lane & 7);
    const int acol = (lane >> 4) * 8;
    const int brow = (lane >> 4) * 8 + (lane & 7);
    const int bcol = ((lane >> 3) & 1) * 8;

    const uint32_t sA = smem_u32(smb);
    const uint32_t oAH = (uint32_t)(((wm * 32 + arow) * GP_PAD + acol) * 2);
    const uint32_t oAL = oAH + GP_OPB;
    const uint32_t oBH = 2u * GP_OPB + (uint32_t)(((wn * 64 + brow) * GP_PAD + bcol) * 2);
    const uint32_t oBL = oBH + GP_OPB;

    const int lrow = tid >> 1;
    const int lhalf = (tid & 1) * 16;
    const uint32_t sdo = (uint32_t)((lrow * GP_PAD + lhalf) * 2);
    const size_t gro = (size_t)lrow * 256;

    auto issue_chunk = [&](int kc, int buf) {
        const uint32_t st = sA + (uint32_t)buf * GP_STAGE + sdo;
        const size_t gs = gro + kc * 32 + lhalf;
#pragma unroll
        for (int half = 0; half < 2; ++half) {
            const uint32_t d = st + (uint32_t)(half * 16);
            const size_t s = gs + half * 8;
            cpa16(d,                 pAH + s);
            cpa16(d + GP_OPB,        pAL + s);
            cpa16(d + 2 * GP_OPB,    pBH + s);
            cpa16(d + 3 * GP_OPB,    pBL + s);
        }
    };

    issue_chunk(0, 0); CP_COMMIT();
    issue_chunk(1, 1); CP_COMMIT();

#pragma unroll 1
    for (int kc = 0; kc < 8; ++kc) {
        if (kc < 7) { CP_WAIT1(); } else { CP_WAIT0(); }
        __syncthreads();
        const uint32_t stb = sA + (uint32_t)(kc & 1) * GP_STAGE;
        const uint32_t aAH = stb + oAH, aAL = stb + oAL;
        const uint32_t aBH = stb + oBH, aBL = stb + oBL;

#pragma unroll
        for (int ks = 0; ks < 2; ++ks) {
            const uint32_t koff = (uint32_t)(ks * 16 * 2);
            uint32_t aH0[4], aH1[4], aL0[4], aL1[4];
            ldsm4(aH0[0], aH0[1], aH0[2], aH0[3], aAH + koff);
            ldsm4(aH1[0], aH1[1], aH1[2], aH1[3], aAH + koff + 16 * GP_PAD * 2);
            ldsm4(aL0[0], aL0[1], aL0[2], aL0[3], aAL + koff);
            ldsm4(aL1[0], aL1[1], aL1[2], aL1[3], aAL + koff + 16 * GP_PAD * 2);
            uint32_t bH[8][2], bL[8][2];
#pragma unroll
            for (int pr = 0; pr < 4; ++pr) {
                uint32_t r0, r1, r2, r3;
                ldsm4(r0, r1, r2, r3, aBH + koff + (uint32_t)(pr * 16 * GP_PAD * 2));
                bH[2*pr][0] = r0; bH[2*pr][1] = r1;
                bH[2*pr+1][0] = r2; bH[2*pr+1][1] = r3;
                ldsm4(r0, r1, r2, r3, aBL + koff + (uint32_t)(pr * 16 * GP_PAD * 2));
                bL[2*pr][0] = r0; bL[2*pr][1] = r1;
                bL[2*pr+1][0] = r2; bL[2*pr+1][1] = r3;
            }
            // term-major ordering: dependent hits on each acc are 16 MMAs apart
#pragma unroll
            for (int ni = 0; ni < 8; ++ni) {
                MMA16816(acc[0][ni], aH0, bH[ni][0], bH[ni][1]);
                MMA16816(acc[1][ni], aH1, bH[ni][0], bH[ni][1]);
            }
#pragma unroll
            for (int ni = 0; ni < 8; ++ni) {
                MMA16816(acc[0][ni], aH0, bL[ni][0], bL[ni][1]);
                MMA16816(acc[1][ni], aH1, bL[ni][0], bL[ni][1]);
            }
#pragma unroll
            for (int ni = 0; ni < 8; ++ni) {
                MMA16816(acc[0][ni], aL0, bH[ni][0], bH[ni][1]);
                MMA16816(acc[1][ni], aL1, bH[ni][0], bH[ni][1]);
            }
        }
        __syncthreads();
        if (kc + 2 <= 7) {
            issue_chunk(kc + 2, kc & 1);
            CP_COMMIT();
        }
    }

    if (EPI == 3) {
        const float* maskb = mask + (size_t)z * 1000000;
        float* outb = out + (size_t)z * 1000000;
#pragma unroll
        for (int mi = 0; mi < 2; ++mi) {
#pragma unroll
            for (int hrow = 0; hrow < 2; ++hrow) {
                int gr = m0 + wm * 32 + mi * 16 + (lane >> 2) + hrow * 8;
                bool rok = (gr < 1000);
                float rs = 0.f;
                const float* mrow = maskb + (size_t)gr * 1000;
                float* orow = outb + (size_t)gr * 1000;
#pragma unroll
                for (int ni = 0; ni < 8; ++ni) {
                    int gc = n0 + wn * 64 + ni * 8 + (lane & 3) * 2;
                    if (rok && gc < 1000) {
                        float v0 = acc[mi][ni][hrow * 2 + 0];
                        float v1 = acc[mi][ni][hrow * 2 + 1];
                        float2 m2 = *(const float2*)(mrow + gc);
                        float z0 = ex2f(v0 * (0.125f * LOG2E));
                        float z1 = ex2f(v1 * (0.125f * LOG2E));
                        float t0 = 10.f - 20.f * frcp(z0 + 1.f);
                        float t1 = 10.f - 20.f * frcp(z1 + 1.f);
                        float e0 = ex2f((t0 + m2.x) * LOG2E);
                        float e1 = ex2f((t1 + m2.y) * LOG2E);
                        *(float2*)(orow + gc) = make_float2(e0, e1);
                        rs += e0 + e1;
                    }
                }
                rs += __shfl_xor_sync(0xFFFFFFFFu, rs, 1);
                rs += __shfl_xor_sync(0xFFFFFFFFu, rs, 2);
                if ((lane & 3) == 0 && rok)
                    atomicAdd(&rsum[z * 1000 + gr], rs);
            }
        }
    } else {
        const float sc = 0.25f * LOG2E;
#pragma unroll
        for (int mi = 0; mi < 2; ++mi) {
#pragma unroll
            for (int hrow = 0; hrow < 2; ++hrow) {
                int grow = m0 + wm * 32 + mi * 16 + (lane >> 2) + hrow * 8;
                float av = 0.f;
                if (EPI == 1 && grow < 1000) av = attr[z * 1000 + grow];
#pragma unroll
                for (int ni = 0; ni < 8; ++ni) {
                    int gc = n0 + wn * 64 + ni * 8 + (lane & 3) * 2;
                    float v0 = acc[mi][ni][hrow * 2 + 0];
                    float v1 = acc[mi][ni][hrow * 2 + 1];
                    if (EPI == 1) {
                        v0 = (v0 + av * wql[gc]) * sc;
                        v1 = (v1 + av * wql[gc + 1]) * sc;
                    }
                    if (EPI == 2) {
                        v0 += bias[gc];
                        v1 += bias[gc + 1];
                    }
                    size_t off = ((size_t)z * 1024 + grow) * ldc + gc;
                    split_store2(CH, CL, off, v0, v1);
                }
            }
        }
    }
}

// ---------------- HMMA flash attention (term-major S ordering) ----------------
#define AT_BUFSZ 71680
#define AT_SMEM  (36864 + 2 * AT_BUFSZ)

__global__ void __launch_bounds__(256, 1)
attn_mma(const float* __restrict__ mask)
{
    extern __shared__ __align__(16) char atsm[];
    const uint32_t sb = smem_u32(atsm);
    const int tid = threadIdx.x, lane = tid & 31, w = tid >> 5;
    const int p0 = blockIdx.x * 128;
    const int hg = blockIdx.y;
    const int b  = blockIdx.z;

    const __nv_bfloat16* gQHp = g_QH + ((size_t)b * 1024 + p0) * 256 + hg * 64;
    const __nv_bfloat16* gQLp = g_QL + ((size_t)b * 1024 + p0) * 256 + hg * 64;
    const float* gM = mask + (size_t)b * 1000000;

    auto issue_tile = [&](int nt, int buf) {
        const int n0 = nt * 64;
        const uint32_t base = sb + 36864u + (uint32_t)buf * AT_BUFSZ;
#pragma unroll
        for (int i = 0; i < 2; ++i) {
            int idx = i * 256 + tid, row = idx >> 3, c = idx & 7;
            size_t srow = (size_t)(b * 1024 + n0 + row) * 512;
            uint32_t doff = (uint32_t)((row * 72 + c * 8) * 2);
            cpa16(base + doff,          g_KVH + srow + hg*64 + c*8);
            cpa16(base + 9216 + doff,   g_KVL + srow + hg*64 + c*8);
            cpa16(base + 18432 + doff,  g_KVH + srow + 256 + hg*64 + c*8);
            cpa16(base + 27648 + doff,  g_KVL + srow + 256 + hg*64 + c*8);
        }
#pragma unroll
        for (int i = 0; i < 8; ++i) {
            int idx = i * 256 + tid, row = idx >> 4, c = idx & 15;
            int gr = p0 + row, gc = n0 + c * 4;
            bool ok = (gr < 1000) && (gc < 1000);
            const float* src = ok ? (gM + (size_t)gr * 1000 + gc) : gM;
            cpa16p(base + 36864u + (uint32_t)((row * 68 + c * 4) * 4), src, ok ? 16 : 0);
        }
    };

#pragma unroll
    for (int i = 0; i < 4; ++i) {
        int idx = i * 256 + tid, row = idx >> 3, c = idx & 7;
        uint32_t doff = (uint32_t)((row * 72 + c * 8) * 2);
        cpa16(sb + doff,          gQHp + (size_t)row * 256 + c * 8);
        cpa16(sb + 18432 + doff,  gQLp + (size_t)row * 256 + c * 8);
    }
    issue_tile(0, 0);
    CP_COMMIT();
    issue_tile(1, 1);
    CP_COMMIT();

    const int qrow = w * 16 + (lane & 7) + ((lane >> 3) & 1) * 8;
    const int qcol = ((lane >> 4) & 1) * 8;
    const int krow = (lane & 7) + ((lane >> 4) & 1) * 8;
    const int kcol = ((lane >> 3) & 1) * 8;
    const int vrow = (lane & 7) + ((lane >> 3) & 1) * 8;
    const int vcol = ((lane >> 4) & 1) * 8;

    uint32_t qh[4][4], ql[4][4];
    float out[4][2][4];
    float denA[4], denB[4];
#pragma unroll
    for (int h = 0; h < 4; ++h) {
        denA[h] = 0.f; denB[h] = 0.f;
#pragma unroll
        for (int d = 0; d < 2; ++d)
#pragma unroll
            for (int q = 0; q < 4; ++q) out[h][d][q] = 0.f;
    }

#pragma unroll 1
    for (int nt = 0; nt < 16; ++nt) {
        if (nt < 15) { CP_WAIT1(); } else { CP_WAIT0(); }
        __syncthreads();

        const uint32_t bufb = sb + 36864u + (uint32_t)(nt & 1) * AT_BUFSZ;
        const uint32_t aM = bufb + 36864u;

        if (nt == 0) {
            const uint32_t aQ = sb + (uint32_t)((qrow * 72 + qcol) * 2);
#pragma unroll
            for (int h = 0; h < 4; ++h) {
                ldsm4(qh[h][0], qh[h][1], qh[h][2], qh[h][3], aQ + (uint32_t)(h * 32));
                ldsm4(ql[h][0], ql[h][1], ql[h][2], ql[h][3], aQ + 18432u + (uint32_t)(h * 32));
            }
        }
        if (nt == 15) {
            for (int i = tid; i < 3072; i += 256) {
                int row = i / 24, c = 40 + (i - row * 24);
                asm volatile("st.shared.f32 [%0],%1;"
                             :: "r"(aM + (uint32_t)((row * 68 + c) * 4)), "f"(-1e30f));
            }
            __syncthreads();
        }

        float mk[8][4];
        {
            uint32_t ab = aM + (uint32_t)((((w * 16) + (lane >> 2)) * 68 + (lane & 3) * 2) * 4);
#pragma unroll
            for (int j = 0; j < 8; ++j) {
                asm volatile("ld.shared.v2.f32 {%0,%1},[%2];"
                             : "=f"(mk[j][0]), "=f"(mk[j][1]) : "r"(ab + (uint32_t)(j * 32)));
                asm volatile("ld.shared.v2.f32 {%0,%1},[%2];"
                             : "=f"(mk[j][2]), "=f"(mk[j][3]) : "r"(ab + (uint32_t)(j * 32 + 2176)));
            }
        }

#pragma unroll
        for (int h = 0; h < 4; ++h) {
            const uint32_t aK = bufb + (uint32_t)(((krow) * 72 + h * 16 + kcol) * 2);
            uint32_t kh[8][2], kl[8][2];
#pragma unroll
            for (int jj = 0; jj < 4; ++jj) {
                ldsm4(kh[2*jj][0], kh[2*jj][1], kh[2*jj+1][0], kh[2*jj+1][1],
                      aK + (uint32_t)(jj * 2304));
                ldsm4(kl[2*jj][0], kl[2*jj][1], kl[2*jj+1][0], kl[2*jj+1][1],
                      aK + 9216u + (uint32_t)(jj * 2304));
            }
            float S[8][4];
            // term-major: dependent hits on each S[j] are 8 MMAs apart
#pragma unroll
            for (int j = 0; j < 8; ++j) {
                S[j][0] = 0.f; S[j][1] = 0.f; S[j][2] = 0.f; S[j][3] = 0.f;
                MMA16816(S[j], qh[h], kh[j][0], kh[j][1]);
            }
#pragma unroll
            for (int j = 0; j < 8; ++j)
                MMA16816(S[j], qh[h], kl[j][0], kl[j][1]);
#pragma unroll
            for (int j = 0; j < 8; ++j)
                MMA16816(S[j], ql[h], kh[j][0], kh[j][1]);

            uint32_t P[8][2];
            float dA = 0.f, dB = 0.f;
#pragma unroll
            for (int j = 0; j < 8; ++j) {
                float e0 = ex2f(fmaf(mk[j][0], LOG2E, S[j][0]));
                float e1 = ex2f(fmaf(mk[j][1], LOG2E, S[j][1]));
                float e2 = ex2f(fmaf(mk[j][2], LOG2E, S[j][2]));
                float e3 = ex2f(fmaf(mk[j][3], LOG2E, S[j][3]));
                dA += e0 + e1; dB += e2 + e3;
                P[j][0] = packbf(e1, e0);
                P[j][1] = packbf(e3, e2);
            }
            denA[h] += dA; denB[h] += dB;
            const uint32_t aV = bufb + 18432u + (uint32_t)(((vrow) * 72 + h * 16 + vcol) * 2);
#pragma unroll
            for (int kc = 0; kc < 4; ++kc) {
                uint32_t Af[4] = {P[2*kc][0], P[2*kc][1], P[2*kc+1][0], P[2*kc+1][1]};
                uint32_t v0, v1, v2, v3;
                ldsm4t(v0, v1, v2, v3, aV + (uint32_t)(kc * 2304));
                MMA16816(out[h][0], Af, v0, v1);
                MMA16816(out[h][1], Af, v2, v3);
                ldsm4t(v0, v1, v2, v3, aV + 9216u + (uint32_t)(kc * 2304));
                MMA16816(out[h][0], Af, v0, v1);
                MMA16816(out[h][1], Af, v2, v3);
            }
        }
        __syncthreads();
        if (nt + 2 <= 15) {
            issue_tile(nt + 2, nt & 1);
            CP_COMMIT();
        }
    }

    const int prA = p0 + w * 16 + (lane >> 2);
    const int prB = prA + 8;
#pragma unroll
    for (int h = 0; h < 4; ++h) {
        float dA = denA[h];
        dA += __shfl_xor_sync(0xFFFFFFFFu, dA, 1);
        dA += __shfl_xor_sync(0xFFFFFFFFu, dA, 2);
        float dB = denB[h];
        dB += __shfl_xor_sync(0xFFFFFFFFu, dB, 1);
        dB += __shfl_xor_sync(0xFFFFFFFFu, dB, 2);
        float iA = frcp(dA), iB = frcp(dB);
        int col = hg * 64 + h * 16 + (lane & 3) * 2;
        if (prA < 1000) {
            size_t off = ((size_t)b * 1024 + prA) * 256 + col;
            split_store2(g_ATH, g_ATL, off,     out[h][0][0] * iA, out[h][0][1] * iA);
            split_store2(g_ATH, g_ATL, off + 8, out[h][1][0] * iA, out[h][1][1] * iA);
        }
        if (prB < 1000) {
            size_t off = ((size_t)b * 1024 + prB) * 256 + col;
            split_store2(g_ATH, g_ATL, off,     out[h][0][2] * iB, out[h][0][3] * iB);
            split_store2(g_ATH, g_ATL, off + 8, out[h][1][2] * iB, out[h][1][3] * iB);
        }
    }
}

// ---------------- normalize ----------------
__global__ void norm_k(float* __restrict__ out) {
    int row = blockIdx.x;
    int c = threadIdx.x;
    if (c < 250) {
        float inv = 1.0f / g_ROWSUM[row];
        float4* p = (float4*)(out + (size_t)row * 1000);
        float4 v = p[c];
        v.x *= inv; v.y *= inv; v.z *= inv; v.w *= inv;
        p[c] = v;
    }
}

// ---------------- launch ----------------
extern "C" void kernel_launch(void* const* d_in, const int* in_sizes, int n_in,
                              void* d_out, int out_size)
{
    const float* last  = (const float*)d_in[0];
    const float* attr  = (const float*)d_in[1];
    const float* mask  = (const float*)d_in[2];
    const float* nodes = (const float*)d_in[3];
    const float* Wq    = (const float*)d_in[4];
    const float* Wk    = (const float*)d_in[5];
    const float* Wv    = (const float*)d_in[6];
    const float* Wc    = (const float*)d_in[7];
    const float* bc    = (const float*)d_in[8];
    float* out = (float*)d_out;

    void* p;
    cudaGetSymbolAddress(&p, g_ROWSUM); float* gRS = (float*)p;
    cudaGetSymbolAddress(&p, g_AH);     __nv_bfloat16* gAH = (__nv_bfloat16*)p;
    cudaGetSymbolAddress(&p, g_AL);     __nv_bfloat16* gAL = (__nv_bfloat16*)p;
    cudaGetSymbolAddress(&p, g_BH);     __nv_bfloat16* gBH = (__nv_bfloat16*)p;
    cudaGetSymbolAddress(&p, g_BL);     __nv_bfloat16* gBL = (__nv_bfloat16*)p;
    cudaGetSymbolAddress(&p, g_QH);     __nv_bfloat16* gQH = (__nv_bfloat16*)p;
    cudaGetSymbolAddress(&p, g_QL);     __nv_bfloat16* gQL = (__nv_bfloat16*)p;
    cudaGetSymbolAddress(&p, g_LH);     __nv_bfloat16* gLH = (__nv_bfloat16*)p;
    cudaGetSymbolAddress(&p, g_LL);     __nv_bfloat16* gLL = (__nv_bfloat16*)p;
    cudaGetSymbolAddress(&p, g_WKVTH);  __nv_bfloat16* gWKVTH = (__nv_bfloat16*)p;
    cudaGetSymbolAddress(&p, g_WKVTL);  __nv_bfloat16* gWKVTL = (__nv_bfloat16*)p;
    cudaGetSymbolAddress(&p, g_WQTH);   __nv_bfloat16* gWQTH = (__nv_bfloat16*)p;
    cudaGetSymbolAddress(&p, g_WQTL);   __nv_bfloat16* gWQTL = (__nv_bfloat16*)p;
    cudaGetSymbolAddress(&p, g_WCTH);   __nv_bfloat16* gWCTH = (__nv_bfloat16*)p;
    cudaGetSymbolAddress(&p, g_WCTL);   __nv_bfloat16* gWCTL = (__nv_bfloat16*)p;
    cudaGetSymbolAddress(&p, g_KVH);    __nv_bfloat16* gKVH = (__nv_bfloat16*)p;
    cudaGetSymbolAddress(&p, g_KVL);    __nv_bfloat16* gKVL = (__nv_bfloat16*)p;
    cudaGetSymbolAddress(&p, g_ATH);    __nv_bfloat16* gATH = (__nv_bfloat16*)p;
    cudaGetSymbolAddress(&p, g_ATL);    __nv_bfloat16* gATL = (__nv_bfloat16*)p;

    cudaFuncSetAttribute(mma_gemm<0>, cudaFuncAttributeMaxDynamicSharedMemorySize, G3_SMEM);
    cudaFuncSetAttribute(mma_gemm<1>, cudaFuncAttributeMaxDynamicSharedMemorySize, G3_SMEM);
    cudaFuncSetAttribute(mma_gemm<2>, cudaFuncAttributeMaxDynamicSharedMemorySize, G3_SMEM);
    cudaFuncSetAttribute(mma_gemm<3>, cudaFuncAttributeMaxDynamicSharedMemorySize, G3_SMEM);
    cudaFuncSetAttribute(attn_mma, cudaFuncAttributeMaxDynamicSharedMemorySize, AT_SMEM);

    prep0_k<<<447, 256>>>();
    tsplit_k<<<1024, 256>>>(Wk, Wv, Wq, Wc);
    splitg2_k<<<8192, 256>>>(nodes, last);

    mma_gemm<0><<<dim3(4, 8, 16), 256, G3_SMEM>>>(
        gBH, gBL, gWKVTH, gWKVTL, gKVH, gKVL, 512,
        nullptr, nullptr, nullptr, nullptr, nullptr, nullptr);
    mma_gemm<1><<<dim3(2, 8, 16), 256, G3_SMEM>>>(
        gLH, gLL, gWQTH, gWQTL, gQH, gQL, 256,
        attr, Wq + 256 * 256, nullptr, nullptr, nullptr, nullptr);

    attn_mma<<<dim3(8, 4, 16), 256, AT_SMEM>>>(mask);

    mma_gemm<2><<<dim3(2, 8, 16), 256, G3_SMEM>>>(
        gATH, gATL, gWCTH, gWCTL, gAH, gAL, 256,
        nullptr, nullptr, bc, nullptr, nullptr, nullptr);

    mma_gemm<3><<<dim3(8, 8, 16), 256, G3_SMEM>>>(
        gAH, gAL, gBH, gBL, nullptr, nullptr, 1000,
        nullptr, nullptr, nullptr, mask, out, gRS);

    norm_k<<<MROWS, 256>>>(out);
}

// round 13
// speedup vs baseline: 1.0125x; 1.0125x over previous
#include <cuda_runtime.h>
#include <cuda_bf16.h>
#include <math.h>
#include <cstdint>

// B=16, P=1000, N=1000, E=256, H=16, D=16, HD=256
#define BSZ   16
#define PN    1000
#define MROWS (BSZ * PN)
#define LOG2E 1.4426950408889634f

__device__ __forceinline__ float ex2f(float x) {
    float y; asm("ex2.approx.f32 %0,%1;" : "=f"(y) : "f"(x)); return y;
}
__device__ __forceinline__ float frcp(float x) {
    float y; asm("rcp.approx.f32 %0,%1;" : "=f"(y) : "f"(x)); return y;
}
__device__ __forceinline__ uint32_t smem_u32(const void* p) {
    uint32_t a;
    asm("{ .reg .u64 t; cvta.to.shared.u64 t, %1; cvt.u32.u64 %0, t; }"
        : "=r"(a) : "l"(p));
    return a;
}
__device__ __forceinline__ void ldsm4(uint32_t& r0, uint32_t& r1,
                                      uint32_t& r2, uint32_t& r3, uint32_t a) {
    asm volatile("ldmatrix.sync.aligned.m8n8.x4.shared.b16 {%0,%1,%2,%3},[%4];"
                 : "=r"(r0), "=r"(r1), "=r"(r2), "=r"(r3) : "r"(a));
}
__device__ __forceinline__ void ldsm4t(uint32_t& r0, uint32_t& r1,
                                       uint32_t& r2, uint32_t& r3, uint32_t a) {
    asm volatile("ldmatrix.sync.aligned.m8n8.x4.trans.shared.b16 {%0,%1,%2,%3},[%4];"
                 : "=r"(r0), "=r"(r1), "=r"(r2), "=r"(r3) : "r"(a));
}
__device__ __forceinline__ uint32_t packbf(float hi, float lo) {
    uint32_t r; asm("cvt.rn.bf16x2.f32 %0,%1,%2;" : "=r"(r) : "f"(hi), "f"(lo));
    return r;
}
__device__ __forceinline__ void cpa16(uint32_t dst, const void* src) {
    asm volatile("cp.async.cg.shared.global [%0],[%1],16;"
                 :: "r"(dst), "l"(src) : "memory");
}
__device__ __forceinline__ void cpa16p(uint32_t dst, const void* src, int n) {
    asm volatile("cp.async.cg.shared.global [%0],[%1],16,%2;"
                 :: "r"(dst), "l"(src), "r"(n) : "memory");
}
#define MMA16816(C, A, B0, B1) \
    asm volatile("mma.sync.aligned.m16n8k16.row.col.f32.bf16.bf16.f32 " \
        "{%0,%1,%2,%3},{%4,%5,%6,%7},{%8,%9},{%0,%1,%2,%3};" \
        : "+f"((C)[0]), "+f"((C)[1]), "+f"((C)[2]), "+f"((C)[3]) \
        : "r"((A)[0]), "r"((A)[1]), "r"((A)[2]), "r"((A)[3]), \
          "r"(B0), "r"(B1))
#define CP_COMMIT() asm volatile("cp.async.commit_group;" ::: "memory")
#define CP_WAIT1()  asm volatile("cp.async.wait_group 1;" ::: "memory")
#define CP_WAIT0()  asm volatile("cp.async.wait_group 0;" ::: "memory")

__device__ __forceinline__ void split_store2(__nv_bfloat16* __restrict__ H,
                                             __nv_bfloat16* __restrict__ L,
                                             size_t off, float v0, float v1) {
    __nv_bfloat16 h0 = __float2bfloat16_rn(v0);
    __nv_bfloat16 h1 = __float2bfloat16_rn(v1);
    __nv_bfloat16 l0 = __float2bfloat16_rn(v0 - __bfloat162float(h0));
    __nv_bfloat16 l1 = __float2bfloat16_rn(v1 - __bfloat162float(h1));
    ushort2 hh, ll;
    hh.x = __bfloat16_as_ushort(h0); hh.y = __bfloat16_as_ushort(h1);
    ll.x = __bfloat16_as_ushort(l0); ll.y = __bfloat16_as_ushort(l1);
    *(ushort2*)(H + off) = hh;
    *(ushort2*)(L + off) = ll;
}

// ---------------- scratch ----------------
__device__ float g_ROWSUM[MROWS];
__device__ __nv_bfloat16 g_AH[16 * 1024 * 256];
__device__ __nv_bfloat16 g_AL[16 * 1024 * 256];
__device__ __nv_bfloat16 g_BH[16 * 1024 * 256];
__device__ __nv_bfloat16 g_BL[16 * 1024 * 256];
__device__ __nv_bfloat16 g_QH[16 * 1024 * 256];
__device__ __nv_bfloat16 g_QL[16 * 1024 * 256];
__device__ __nv_bfloat16 g_KVH[16 * 1024 * 512];
__device__ __nv_bfloat16 g_KVL[16 * 1024 * 512];
__device__ __nv_bfloat16 g_LH[16 * 1024 * 256];
__device__ __nv_bfloat16 g_LL[16 * 1024 * 256];
__device__ __nv_bfloat16 g_ATH[16 * 1024 * 256];
__device__ __nv_bfloat16 g_ATL[16 * 1024 * 256];
__device__ __nv_bfloat16 g_WKVTH[512 * 256];
__device__ __nv_bfloat16 g_WKVTL[512 * 256];
__device__ __nv_bfloat16 g_WQTH[256 * 256];
__device__ __nv_bfloat16 g_WQTL[256 * 256];
__device__ __nv_bfloat16 g_WCTH[256 * 256];
__device__ __nv_bfloat16 g_WCTL[256 * 256];

__global__ void prep0_k() {
    int i = blockIdx.x * 256 + threadIdx.x;
    if (i < MROWS) {
        g_ROWSUM[i] = 0.f;
    } else if (i < MROWS + 98304) {
        int j = i - MROWS;
        int z = j / 6144, rem = j % 6144;
        int r = 1000 + (rem >> 8), c = rem & 255;
        size_t off = ((size_t)z * 1024 + r) * 256 + c;
        g_ATH[off] = __ushort_as_bfloat16(0);
        g_ATL[off] = __ushort_as_bfloat16(0);
    }
}

__global__ void tsplit_k(const float* __restrict__ Wk, const float* __restrict__ Wv,
                         const float* __restrict__ Wq, const float* __restrict__ Wc)
{
    int idx = blockIdx.x * 256 + threadIdx.x;
    float v; __nv_bfloat16 *H, *L; int off;
    if (idx < 131072) {
        int n = idx >> 8, k = idx & 255;
        v = (n < 256) ? Wk[k * 256 + n] : Wv[k * 256 + (n - 256)];
        H = g_WKVTH; L = g_WKVTL; off = idx;
    } else if (idx < 196608) {
        int i = idx - 131072;
        int n = i >> 8, k = i & 255;
        v = Wq[k * 256 + n];
        H = g_WQTH; L = g_WQTL; off = i;
    } else {
        int i = idx - 196608;
        int n = i >> 8, k = i & 255;
        v = Wc[k * 256 + n];
        H = g_WCTH; L = g_WCTL; off = i;
    }
    __nv_bfloat16 h = __float2bfloat16_rn(v);
    __nv_bfloat16 l = __float2bfloat16_rn(v - __bfloat162float(h));
    H[off] = h; L[off] = l;
}

__global__ void splitg2_k(const float* __restrict__ nodes, const float* __restrict__ last)
{
    int i = blockIdx.x * 256 + threadIdx.x;
    const float* src = nodes;
    __nv_bfloat16* H = g_BH;
    __nv_bfloat16* L = g_BL;
    if (i >= 1048576) {
        i -= 1048576;
        src = last; H = g_LH; L = g_LL;
    }
    int c4 = i & 63;
    int zr = i >> 6;
    int z = zr >> 10, r = zr & 1023;
    float4 v = make_float4(0.f, 0.f, 0.f, 0.f);
    if (r < 1000)
        v = *(const float4*)(src + ((size_t)z * 1000 + r) * 256 + c4 * 4);
    float xs[4] = {v.x, v.y, v.z, v.w};
    ushort4 hh, ll;
    unsigned short* hp = &hh.x;
    unsigned short* lp = &ll.x;
#pragma unroll
    for (int j = 0; j < 4; ++j) {
        __nv_bfloat16 h = __float2bfloat16_rn(xs[j]);
        float res = xs[j] - __bfloat162float(h);
        __nv_bfloat16 l = __float2bfloat16_rn(res);
        hp[j] = __bfloat16_as_ushort(h);
        lp[j] = __bfloat16_as_ushort(l);
    }
    *(ushort4*)(H + (size_t)zr * 256 + c4 * 4) = hh;
    *(ushort4*)(L + (size_t)zr * 256 + c4 * 4) = ll;
}

// ---------------- merged HMMA GEMM (R11/R12 proven) ----------------
#define GP_PAD    40
#define GP_TILE   (128 * GP_PAD)
#define GP_OPB    (GP_TILE * 2)
#define GP_STAGE  (4 * GP_OPB)
#define G3_SMEM   (2 * GP_STAGE)

template <int EPI>
__global__ void __launch_bounds__(256, 2)
mma_gemm(const __nv_bfloat16* __restrict__ AH, const __nv_bfloat16* __restrict__ AL,
         const __nv_bfloat16* __restrict__ BH, const __nv_bfloat16* __restrict__ BL,
         __nv_bfloat16* __restrict__ CH, __nv_bfloat16* __restrict__ CL, int ldc,
         const float* __restrict__ attr, const float* __restrict__ wql,
         const float* __restrict__ bias,
         const float* __restrict__ mask, float* __restrict__ out,
         float* __restrict__ rsum)
{
    extern __shared__ __align__(16) __nv_bfloat16 smb[];

    const int tid = threadIdx.x;
    const int lane = tid & 31;
    const int w = tid >> 5;
    const int wm = w & 3, wn = w >> 2;
    const int z = blockIdx.z, m0 = blockIdx.y * 128, n0 = blockIdx.x * 128;

    const __nv_bfloat16* pAH = AH + ((size_t)z * 1024 + m0) * 256;
    const __nv_bfloat16* pAL = AL + ((size_t)z * 1024 + m0) * 256;
    const size_t boff = (EPI == 3) ? ((size_t)z * 1024 + n0) * 256 : (size_t)n0 * 256;
    const __nv_bfloat16* pBH = BH + boff;
    const __nv_bfloat16* pBL = BL + boff;

    float acc[2][8][4];
#pragma unroll
    for (int mi = 0; mi < 2; ++mi)
#pragma unroll
        for (int ni = 0; ni < 8; ++ni)
#pragma unroll
            for (int q = 0; q < 4; ++q) acc[mi][ni][q] = 0.f;

    const int arow = ((lane >> 3) & 1) * 8 + (lane & 7);
    const int acol = (lane >> 4) * 8;
    const int brow = (lane >> 4) * 8 + (lane & 7);
    const int bcol = ((lane >> 3) & 1) * 8;

    const uint32_t sA = smem_u32(smb);
    const uint32_t oAH = (uint32_t)(((wm * 32 + arow) * GP_PAD + acol) * 2);
    const uint32_t oAL = oAH + GP_OPB;
    const uint32_t oBH = 2u * GP_OPB + (uint32_t)(((wn * 64 + brow) * GP_PAD + bcol) * 2);
    const uint32_t oBL = oBH + GP_OPB;

    const int lrow = tid >> 1;
    const int lhalf = (tid & 1) * 16;
    const uint32_t sdo = (uint32_t)((lrow * GP_PAD + lhalf) * 2);
    const size_t gro = (size_t)lrow * 256;

    auto issue_chunk = [&](int kc, int buf) {
        const uint32_t st = sA + (uint32_t)buf * GP_STAGE + sdo;
        const size_t gs = gro + kc * 32 + lhalf;
#pragma unroll
        for (int half = 0; half < 2; ++half) {
            const uint32_t d = st + (uint32_t)(half * 16);
            const size_t s = gs + half * 8;
            cpa16(d,                 pAH + s);
            cpa16(d + GP_OPB,        pAL + s);
            cpa16(d + 2 * GP_OPB,    pBH + s);
            cpa16(d + 3 * GP_OPB,    pBL + s);
        }
    };

    issue_chunk(0, 0); CP_COMMIT();
    issue_chunk(1, 1); CP_COMMIT();

#pragma unroll 1
    for (int kc = 0; kc < 8; ++kc) {
        if (kc < 7) { CP_WAIT1(); } else { CP_WAIT0(); }
        __syncthreads();
        const uint32_t stb = sA + (uint32_t)(kc & 1) * GP_STAGE;
        const uint32_t aAH = stb + oAH, aAL = stb + oAL;
        const uint32_t aBH = stb + oBH, aBL = stb + oBL;

#pragma unroll
        for (int ks = 0; ks < 2; ++ks) {
            const uint32_t koff = (uint32_t)(ks * 16 * 2);
            uint32_t aH0[4], aH1[4], aL0[4], aL1[4];
            ldsm4(aH0[0], aH0[1], aH0[2], aH0[3], aAH + koff);
            ldsm4(aH1[0], aH1[1], aH1[2], aH1[3], aAH + koff + 16 * GP_PAD * 2);
            ldsm4(aL0[0], aL0[1], aL0[2], aL0[3], aAL + koff);
            ldsm4(aL1[0], aL1[1], aL1[2], aL1[3], aAL + koff + 16 * GP_PAD * 2);
            uint32_t bH[8][2], bL[8][2];
#pragma unroll
            for (int pr = 0; pr < 4; ++pr) {
                uint32_t r0, r1, r2, r3;
                ldsm4(r0, r1, r2, r3, aBH + koff + (uint32_t)(pr * 16 * GP_PAD * 2));
                bH[2*pr][0] = r0; bH[2*pr][1] = r1;
                bH[2*pr+1][0] = r2; bH[2*pr+1][1] = r3;
                ldsm4(r0, r1, r2, r3, aBL + koff + (uint32_t)(pr * 16 * GP_PAD * 2));
                bL[2*pr][0] = r0; bL[2*pr][1] = r1;
                bL[2*pr+1][0] = r2; bL[2*pr+1][1] = r3;
            }
#pragma unroll
            for (int ni = 0; ni < 8; ++ni) {
                MMA16816(acc[0][ni], aH0, bH[ni][0], bH[ni][1]);
                MMA16816(acc[1][ni], aH1, bH[ni][0], bH[ni][1]);
            }
#pragma unroll
            for (int ni = 0; ni < 8; ++ni) {
                MMA16816(acc[0][ni], aH0, bL[ni][0], bL[ni][1]);
                MMA16816(acc[1][ni], aH1, bL[ni][0], bL[ni][1]);
            }
#pragma unroll
            for (int ni = 0; ni < 8; ++ni) {
                MMA16816(acc[0][ni], aL0, bH[ni][0], bH[ni][1]);
                MMA16816(acc[1][ni], aL1, bH[ni][0], bH[ni][1]);
            }
        }
        __syncthreads();
        if (kc + 2 <= 7) {
            issue_chunk(kc + 2, kc & 1);
            CP_COMMIT();
        }
    }

    if (EPI == 3) {
        const float* maskb = mask + (size_t)z * 1000000;
        float* outb = out + (size_t)z * 1000000;
#pragma unroll
        for (int mi = 0; mi < 2; ++mi) {
#pragma unroll
            for (int hrow = 0; hrow < 2; ++hrow) {
                int gr = m0 + wm * 32 + mi * 16 + (lane >> 2) + hrow * 8;
                bool rok = (gr < 1000);
                float rs = 0.f;
                const float* mrow = maskb + (size_t)gr * 1000;
                float* orow = outb + (size_t)gr * 1000;
#pragma unroll
                for (int ni = 0; ni < 8; ++ni) {
                    int gc = n0 + wn * 64 + ni * 8 + (lane & 3) * 2;
                    if (rok && gc < 1000) {
                        float v0 = acc[mi][ni][hrow * 2 + 0];
                        float v1 = acc[mi][ni][hrow * 2 + 1];
                        float2 m2 = *(const float2*)(mrow + gc);
                        float z0 = ex2f(v0 * (0.125f * LOG2E));
                        float z1 = ex2f(v1 * (0.125f * LOG2E));
                        float t0 = 10.f - 20.f * frcp(z0 + 1.f);
                        float t1 = 10.f - 20.f * frcp(z1 + 1.f);
                        float e0 = ex2f((t0 + m2.x) * LOG2E);
                        float e1 = ex2f((t1 + m2.y) * LOG2E);
                        *(float2*)(orow + gc) = make_float2(e0, e1);
                        rs += e0 + e1;
                    }
                }
                rs += __shfl_xor_sync(0xFFFFFFFFu, rs, 1);
                rs += __shfl_xor_sync(0xFFFFFFFFu, rs, 2);
                if ((lane & 3) == 0 && rok)
                    atomicAdd(&rsum[z * 1000 + gr], rs);
            }
        }
    } else {
        const float sc = 0.25f * LOG2E;
#pragma unroll
        for (int mi = 0; mi < 2; ++mi) {
#pragma unroll
            for (int hrow = 0; hrow < 2; ++hrow) {
                int grow = m0 + wm * 32 + mi * 16 + (lane >> 2) + hrow * 8;
                float av = 0.f;
                if (EPI == 1 && grow < 1000) av = attr[z * 1000 + grow];
#pragma unroll
                for (int ni = 0; ni < 8; ++ni) {
                    int gc = n0 + wn * 64 + ni * 8 + (lane & 3) * 2;
                    float v0 = acc[mi][ni][hrow * 2 + 0];
                    float v1 = acc[mi][ni][hrow * 2 + 1];
                    if (EPI == 1) {
                        v0 = (v0 + av * wql[gc]) * sc;
                        v1 = (v1 + av * wql[gc + 1]) * sc;
                    }
                    if (EPI == 2) {
                        v0 += bias[gc];
                        v1 += bias[gc + 1];
                    }
                    size_t off = ((size_t)z * 1024 + grow) * ldc + gc;
                    split_store2(CH, CL, off, v0, v1);
                }
            }
        }
    }
}

// ---------------- HMMA flash attention: 32-wide n-tiles, 2 CTAs/SM ----------------
// buffer: KH@0, KL@4608, VH@9216, VL@13824 ([32][72] bf16 each), mask@18432 ([128][36] f32)
#define AT_BUFSZ 36864
#define AT_SMEM  (36864 + 2 * AT_BUFSZ)   // 110592

__global__ void __launch_bounds__(256, 2)
attn_mma(const float* __restrict__ mask)
{
    extern __shared__ __align__(16) char atsm[];
    const uint32_t sb = smem_u32(atsm);
    const int tid = threadIdx.x, lane = tid & 31, w = tid >> 5;
    const int p0 = blockIdx.x * 128;
    const int hg = blockIdx.y;
    const int b  = blockIdx.z;

    const __nv_bfloat16* gQHp = g_QH + ((size_t)b * 1024 + p0) * 256 + hg * 64;
    const __nv_bfloat16* gQLp = g_QL + ((size_t)b * 1024 + p0) * 256 + hg * 64;
    const float* gM = mask + (size_t)b * 1000000;

    // KV loader indices: one 16B chunk per operand per thread
    const int kvrow = tid >> 3, kvc = tid & 7;
    const uint32_t kvdoff = (uint32_t)((kvrow * 72 + kvc * 8) * 2);

    auto issue_tile = [&](int nt, int buf) {
        const int n0 = nt * 32;
        const uint32_t base = sb + 36864u + (uint32_t)buf * AT_BUFSZ;
        size_t srow = (size_t)(b * 1024 + n0 + kvrow) * 512;
        cpa16(base + kvdoff,          g_KVH + srow + hg*64 + kvc*8);
        cpa16(base + 4608 + kvdoff,   g_KVL + srow + hg*64 + kvc*8);
        cpa16(base + 9216 + kvdoff,   g_KVH + srow + 256 + hg*64 + kvc*8);
        cpa16(base + 13824 + kvdoff,  g_KVL + srow + 256 + hg*64 + kvc*8);
#pragma unroll
        for (int i = 0; i < 4; ++i) {
            int idx = i * 256 + tid, row = idx >> 3, c = idx & 7;
            int gr = p0 + row, gc = n0 + c * 4;
            bool ok = (gr < 1000) && (gc < 1000);
            const float* src = ok ? (gM + (size_t)gr * 1000 + gc) : gM;
            cpa16p(base + 18432u + (uint32_t)((row * 36 + c * 4) * 4), src, ok ? 16 : 0);
        }
    };

    // Q into resident smem (QH @ sb, QL @ sb+18432)
#pragma unroll
    for (int i = 0; i < 4; ++i) {
        int idx = i * 256 + tid, row = idx >> 3, c = idx & 7;
        uint32_t doff = (uint32_t)((row * 72 + c * 8) * 2);
        cpa16(sb + doff,          gQHp + (size_t)row * 256 + c * 8);
        cpa16(sb + 18432 + doff,  gQLp + (size_t)row * 256 + c * 8);
    }
    issue_tile(0, 0);
    CP_COMMIT();
    issue_tile(1, 1);
    CP_COMMIT();

    const int qrow = w * 16 + (lane & 7) + ((lane >> 3) & 1) * 8;
    const int qcol = ((lane >> 4) & 1) * 8;
    const int krow = (lane & 7) + ((lane >> 4) & 1) * 8;
    const int kcol = ((lane >> 3) & 1) * 8;
    const int vrow = (lane & 7) + ((lane >> 3) & 1) * 8;
    const int vcol = ((lane >> 4) & 1) * 8;

    const uint32_t aQ = sb + (uint32_t)((qrow * 72 + qcol) * 2);

    float out[4][2][4];
    float denA[4], denB[4];
#pragma unroll
    for (int h = 0; h < 4; ++h) {
        denA[h] = 0.f; denB[h] = 0.f;
#pragma unroll
        for (int d = 0; d < 2; ++d)
#pragma unroll
            for (int q = 0; q < 4; ++q) out[h][d][q] = 0.f;
    }

#pragma unroll 1
    for (int nt = 0; nt < 32; ++nt) {
        if (nt < 31) { CP_WAIT1(); } else { CP_WAIT0(); }
        __syncthreads();

        const uint32_t bufb = sb + 36864u + (uint32_t)(nt & 1) * AT_BUFSZ;
        const uint32_t aM = bufb + 18432u;

        if (nt == 31) {
            // patch mask cols n >= 1000 (n0=992: cols 8..31)
            for (int i = tid; i < 3072; i += 256) {
                int row = i / 24, c = 8 + (i - row * 24);
                asm volatile("st.shared.f32 [%0],%1;"
                             :: "r"(aM + (uint32_t)((row * 36 + c) * 4)), "f"(-1e30f));
            }
            __syncthreads();
        }

        float mk[4][4];
        {
            uint32_t ab = aM + (uint32_t)((((w * 16) + (lane >> 2)) * 36 + (lane & 3) * 2) * 4);
#pragma unroll
            for (int j = 0; j < 4; ++j) {
                asm volatile("ld.shared.v2.f32 {%0,%1},[%2];"
                             : "=f"(mk[j][0]), "=f"(mk[j][1]) : "r"(ab + (uint32_t)(j * 32)));
                asm volatile("ld.shared.v2.f32 {%0,%1},[%2];"
                             : "=f"(mk[j][2]), "=f"(mk[j][3]) : "r"(ab + (uint32_t)(j * 32 + 1152)));
            }
        }

#pragma unroll
        for (int h = 0; h < 4; ++h) {
            uint32_t qh[4], ql[4];
            ldsm4(qh[0], qh[1], qh[2], qh[3], aQ + (uint32_t)(h * 32));
            ldsm4(ql[0], ql[1], ql[2], ql[3], aQ + 18432u + (uint32_t)(h * 32));

            const uint32_t aK = bufb + (uint32_t)((krow * 72 + h * 16 + kcol) * 2);
            uint32_t kh[4][2], kl[4][2];
#pragma unroll
            for (int jj = 0; jj < 2; ++jj) {
                uint32_t r0, r1, r2, r3;
                ldsm4(r0, r1, r2, r3, aK + (uint32_t)(jj * 2304));
                kh[2*jj][0] = r0; kh[2*jj][1] = r1;
                kh[2*jj+1][0] = r2; kh[2*jj+1][1] = r3;
                ldsm4(r0, r1, r2, r3, aK + 4608u + (uint32_t)(jj * 2304));
                kl[2*jj][0] = r0; kl[2*jj][1] = r1;
                kl[2*jj+1][0] = r2; kl[2*jj+1][1] = r3;
            }
            float S[4][4];
#pragma unroll
            for (int j = 0; j < 4; ++j) {
                S[j][0] = 0.f; S[j][1] = 0.f; S[j][2] = 0.f; S[j][3] = 0.f;
                MMA16816(S[j], qh, kh[j][0], kh[j][1]);
            }
#pragma unroll
            for (int j = 0; j < 4; ++j)
                MMA16816(S[j], qh, kl[j][0], kl[j][1]);
#pragma unroll
            for (int j = 0; j < 4; ++j)
                MMA16816(S[j], ql, kh[j][0], kh[j][1]);

            uint32_t P[4][2];
            float dA = 0.f, dB = 0.f;
#pragma unroll
            for (int j = 0; j < 4; ++j) {
                float e0 = ex2f(fmaf(mk[j][0], LOG2E, S[j][0]));
                float e1 = ex2f(fmaf(mk[j][1], LOG2E, S[j][1]));
                float e2 = ex2f(fmaf(mk[j][2], LOG2E, S[j][2]));
                float e3 = ex2f(fmaf(mk[j][3], LOG2E, S[j][3]));
                dA += e0 + e1; dB += e2 + e3;
                P[j][0] = packbf(e1, e0);
                P[j][1] = packbf(e3, e2);
            }
            denA[h] += dA; denB[h] += dB;
            const uint32_t aV = bufb + 9216u + (uint32_t)((vrow * 72 + h * 16 + vcol) * 2);
#pragma unroll
            for (int kc = 0; kc < 2; ++kc) {
                uint32_t Af[4] = {P[2*kc][0], P[2*kc][1], P[2*kc+1][0], P[2*kc+1][1]};
                uint32_t v0, v1, v2, v3;
                ldsm4t(v0, v1, v2, v3, aV + (uint32_t)(kc * 2304));
                MMA16816(out[h][0], Af, v0, v1);
                MMA16816(out[h][1], Af, v2, v3);
                ldsm4t(v0, v1, v2, v3, aV + 4608u + (uint32_t)(kc * 2304));
                MMA16816(out[h][0], Af, v0, v1);
                MMA16816(out[h][1], Af, v2, v3);
            }
        }
        __syncthreads();
        if (nt + 2 <= 31) {
            issue_tile(nt + 2, nt & 1);
            CP_COMMIT();
        }
    }

    const int prA = p0 + w * 16 + (lane >> 2);
    const int prB = prA + 8;
#pragma unroll
    for (int h = 0; h < 4; ++h) {
        float dA = denA[h];
        dA += __shfl_xor_sync(0xFFFFFFFFu, dA, 1);
        dA += __shfl_xor_sync(0xFFFFFFFFu, dA, 2);
        float dB = denB[h];
        dB += __shfl_xor_sync(0xFFFFFFFFu, dB, 1);
        dB += __shfl_xor_sync(0xFFFFFFFFu, dB, 2);
        float iA = frcp(dA), iB = frcp(dB);
        int col = hg * 64 + h * 16 + (lane & 3) * 2;
        if (prA < 1000) {
            size_t off = ((size_t)b * 1024 + prA) * 256 + col;
            split_store2(g_ATH, g_ATL, off,     out[h][0][0] * iA, out[h][0][1] * iA);
            split_store2(g_ATH, g_ATL, off + 8, out[h][1][0] * iA, out[h][1][1] * iA);
        }
        if (prB < 1000) {
            size_t off = ((size_t)b * 1024 + prB) * 256 + col;
            split_store2(g_ATH, g_ATL, off,     out[h][0][2] * iB, out[h][0][3] * iB);
            split_store2(g_ATH, g_ATL, off + 8, out[h][1][2] * iB, out[h][1][3] * iB);
        }
    }
}

// ---------------- normalize ----------------
__global__ void norm_k(float* __restrict__ out) {
    int row = blockIdx.x;
    int c = threadIdx.x;
    if (c < 250) {
        float inv = 1.0f / g_ROWSUM[row];
        float4* p = (float4*)(out + (size_t)row * 1000);
        float4 v = p[c];
        v.x *= inv; v.y *= inv; v.z *= inv; v.w *= inv;
        p[c] = v;
    }
}

// ---------------- launch ----------------
extern "C" void kernel_launch(void* const* d_in, const int* in_sizes, int n_in,
                              void* d_out, int out_size)
{
    const float* last  = (const float*)d_in[0];
    const float* attr  = (const float*)d_in[1];
    const float* mask  = (const float*)d_in[2];
    const float* nodes = (const float*)d_in[3];
    const float* Wq    = (const float*)d_in[4];
    const float* Wk    = (const float*)d_in[5];
    const float* Wv    = (const float*)d_in[6];
    const float* Wc    = (const float*)d_in[7];
    const float* bc    = (const float*)d_in[8];
    float* out = (float*)d_out;

    void* p;
    cudaGetSymbolAddress(&p, g_ROWSUM); float* gRS = (float*)p;
    cudaGetSymbolAddress(&p, g_AH);     __nv_bfloat16* gAH = (__nv_bfloat16*)p;
    cudaGetSymbolAddress(&p, g_AL);     __nv_bfloat16* gAL = (__nv_bfloat16*)p;
    cudaGetSymbolAddress(&p, g_BH);     __nv_bfloat16* gBH = (__nv_bfloat16*)p;
    cudaGetSymbolAddress(&p, g_BL);     __nv_bfloat16* gBL = (__nv_bfloat16*)p;
    cudaGetSymbolAddress(&p, g_QH);     __nv_bfloat16* gQH = (__nv_bfloat16*)p;
    cudaGetSymbolAddress(&p, g_QL);     __nv_bfloat16* gQL = (__nv_bfloat16*)p;
    cudaGetSymbolAddress(&p, g_LH);     __nv_bfloat16* gLH = (__nv_bfloat16*)p;
    cudaGetSymbolAddress(&p, g_LL);     __nv_bfloat16* gLL = (__nv_bfloat16*)p;
    cudaGetSymbolAddress(&p, g_WKVTH);  __nv_bfloat16* gWKVTH = (__nv_bfloat16*)p;
    cudaGetSymbolAddress(&p, g_WKVTL);  __nv_bfloat16* gWKVTL = (__nv_bfloat16*)p;
    cudaGetSymbolAddress(&p, g_WQTH);   __nv_bfloat16* gWQTH = (__nv_bfloat16*)p;
    cudaGetSymbolAddress(&p, g_WQTL);   __nv_bfloat16* gWQTL = (__nv_bfloat16*)p;
    cudaGetSymbolAddress(&p, g_WCTH);   __nv_bfloat16* gWCTH = (__nv_bfloat16*)p;
    cudaGetSymbolAddress(&p, g_WCTL);   __nv_bfloat16* gWCTL = (__nv_bfloat16*)p;
    cudaGetSymbolAddress(&p, g_KVH);    __nv_bfloat16* gKVH = (__nv_bfloat16*)p;
    cudaGetSymbolAddress(&p, g_KVL);    __nv_bfloat16* gKVL = (__nv_bfloat16*)p;
    cudaGetSymbolAddress(&p, g_ATH);    __nv_bfloat16* gATH = (__nv_bfloat16*)p;
    cudaGetSymbolAddress(&p, g_ATL);    __nv_bfloat16* gATL = (__nv_bfloat16*)p;

    cudaFuncSetAttribute(mma_gemm<0>, cudaFuncAttributeMaxDynamicSharedMemorySize, G3_SMEM);
    cudaFuncSetAttribute(mma_gemm<1>, cudaFuncAttributeMaxDynamicSharedMemorySize, G3_SMEM);
    cudaFuncSetAttribute(mma_gemm<2>, cudaFuncAttributeMaxDynamicSharedMemorySize, G3_SMEM);
    cudaFuncSetAttribute(mma_gemm<3>, cudaFuncAttributeMaxDynamicSharedMemorySize, G3_SMEM);
    cudaFuncSetAttribute(attn_mma, cudaFuncAttributeMaxDynamicSharedMemorySize, AT_SMEM);

    prep0_k<<<447, 256>>>();
    tsplit_k<<<1024, 256>>>(Wk, Wv, Wq, Wc);
    splitg2_k<<<8192, 256>>>(nodes, last);

    mma_gemm<0><<<dim3(4, 8, 16), 256, G3_SMEM>>>(
        gBH, gBL, gWKVTH, gWKVTL, gKVH, gKVL, 512,
        nullptr, nullptr, nullptr, nullptr, nullptr, nullptr);
    mma_gemm<1><<<dim3(2, 8, 16), 256, G3_SMEM>>>(
        gLH, gLL, gWQTH, gWQTL, gQH, gQL, 256,
        attr, Wq + 256 * 256, nullptr, nullptr, nullptr, nullptr);

    attn_mma<<<dim3(8, 4, 16), 256, AT_SMEM>>>(mask);

    mma_gemm<2><<<dim3(2, 8, 16), 256, G3_SMEM>>>(
        gATH, gATL, gWCTH, gWCTL, gAH, gAL, 256,
        nullptr, nullptr, bc, nullptr, nullptr, nullptr);

    mma_gemm<3><<<dim3(8, 8, 16), 256, G3_SMEM>>>(
        gAH, gAL, gBH, gBL, nullptr, nullptr, 1000,
        nullptr, nullptr, nullptr, mask, out, gRS);

    norm_k<<<MROWS, 256>>>(out);
}

// round 14
// speedup vs baseline: 1.0270x; 1.0144x over previous
#include <cuda_runtime.h>
#include <cuda_bf16.h>
#include <math.h>
#include <cstdint>

// B=16, P=1000, N=1000, E=256, H=16, D=16, HD=256
#define BSZ   16
#define PN    1000
#define MROWS (BSZ * PN)
#define LOG2E 1.4426950408889634f

__device__ __forceinline__ float ex2f(float x) {
    float y; asm("ex2.approx.f32 %0,%1;" : "=f"(y) : "f"(x)); return y;
}
__device__ __forceinline__ float frcp(float x) {
    float y; asm("rcp.approx.f32 %0,%1;" : "=f"(y) : "f"(x)); return y;
}
__device__ __forceinline__ uint32_t smem_u32(const void* p) {
    uint32_t a;
    asm("{ .reg .u64 t; cvta.to.shared.u64 t, %1; cvt.u32.u64 %0, t; }"
        : "=r"(a) : "l"(p));
    return a;
}
__device__ __forceinline__ void ldsm4(uint32_t& r0, uint32_t& r1,
                                      uint32_t& r2, uint32_t& r3, uint32_t a) {
    asm volatile("ldmatrix.sync.aligned.m8n8.x4.shared.b16 {%0,%1,%2,%3},[%4];"
                 : "=r"(r0), "=r"(r1), "=r"(r2), "=r"(r3) : "r"(a));
}
__device__ __forceinline__ void ldsm4t(uint32_t& r0, uint32_t& r1,
                                       uint32_t& r2, uint32_t& r3, uint32_t a) {
    asm volatile("ldmatrix.sync.aligned.m8n8.x4.trans.shared.b16 {%0,%1,%2,%3},[%4];"
                 : "=r"(r0), "=r"(r1), "=r"(r2), "=r"(r3) : "r"(a));
}
__device__ __forceinline__ uint32_t packbf(float hi, float lo) {
    uint32_t r; asm("cvt.rn.bf16x2.f32 %0,%1,%2;" : "=r"(r) : "f"(hi), "f"(lo));
    return r;
}
__device__ __forceinline__ void cpa16(uint32_t dst, const void* src) {
    asm volatile("cp.async.cg.shared.global [%0],[%1],16;"
                 :: "r"(dst), "l"(src) : "memory");
}
__device__ __forceinline__ void cpa16p(uint32_t dst, const void* src, int n) {
    asm volatile("cp.async.cg.shared.global [%0],[%1],16,%2;"
                 :: "r"(dst), "l"(src), "r"(n) : "memory");
}
#define MMA16816(C, A, B0, B1) \
    asm volatile("mma.sync.aligned.m16n8k16.row.col.f32.bf16.bf16.f32 " \
        "{%0,%1,%2,%3},{%4,%5,%6,%7},{%8,%9},{%0,%1,%2,%3};" \
        : "+f"((C)[0]), "+f"((C)[1]), "+f"((C)[2]), "+f"((C)[3]) \
        : "r"((A)[0]), "r"((A)[1]), "r"((A)[2]), "r"((A)[3]), \
          "r"(B0), "r"(B1))
#define CP_COMMIT() asm volatile("cp.async.commit_group;" ::: "memory")
#define CP_WAIT1()  asm volatile("cp.async.wait_group 1;" ::: "memory")
#define CP_WAIT0()  asm volatile("cp.async.wait_group 0;" ::: "memory")

__device__ __forceinline__ void split_store2(__nv_bfloat16* __restrict__ H,
                                             __nv_bfloat16* __restrict__ L,
                                             size_t off, float v0, float v1) {
    __nv_bfloat16 h0 = __float2bfloat16_rn(v0);
    __nv_bfloat16 h1 = __float2bfloat16_rn(v1);
    __nv_bfloat16 l0 = __float2bfloat16_rn(v0 - __bfloat162float(h0));
    __nv_bfloat16 l1 = __float2bfloat16_rn(v1 - __bfloat162float(h1));
    ushort2 hh, ll;
    hh.x = __bfloat16_as_ushort(h0); hh.y = __bfloat16_as_ushort(h1);
    ll.x = __bfloat16_as_ushort(l0); ll.y = __bfloat16_as_ushort(l1);
    *(ushort2*)(H + off) = hh;
    *(ushort2*)(L + off) = ll;
}

// ---------------- scratch ----------------
__device__ float g_ROWSUM[MROWS];
__device__ __nv_bfloat16 g_AH[16 * 1024 * 256];
__device__ __nv_bfloat16 g_AL[16 * 1024 * 256];
__device__ __nv_bfloat16 g_BH[16 * 1024 * 256];
__device__ __nv_bfloat16 g_BL[16 * 1024 * 256];
__device__ __nv_bfloat16 g_QH[16 * 1024 * 256];
__device__ __nv_bfloat16 g_QL[16 * 1024 * 256];
__device__ __nv_bfloat16 g_KVH[16 * 1024 * 512];
__device__ __nv_bfloat16 g_KVL[16 * 1024 * 512];
__device__ __nv_bfloat16 g_LH[16 * 1024 * 256];
__device__ __nv_bfloat16 g_LL[16 * 1024 * 256];
__device__ __nv_bfloat16 g_ATH[16 * 1024 * 256];
__device__ __nv_bfloat16 g_ATL[16 * 1024 * 256];
__device__ __nv_bfloat16 g_WKVTH[512 * 256];
__device__ __nv_bfloat16 g_WKVTL[512 * 256];
__device__ __nv_bfloat16 g_WQTH[256 * 256];
__device__ __nv_bfloat16 g_WQTL[256 * 256];
__device__ __nv_bfloat16 g_WCTH[256 * 256];
__device__ __nv_bfloat16 g_WCTL[256 * 256];

// ---------------- single merged prep kernel ----------------
// [0,16000)               : rowsum zero
// [16000,114304)          : ATH/ATL pad rows zero
// [114304,376448)         : weight transpose+split (262144)
// [376448,2473600)        : activation splits (2 x 1048576 float4 units)
__global__ void prep_all(const float* __restrict__ Wk, const float* __restrict__ Wv,
                         const float* __restrict__ Wq, const float* __restrict__ Wc,
                         const float* __restrict__ nodes, const float* __restrict__ last)
{
    int i = blockIdx.x * 256 + threadIdx.x;
    if (i < MROWS) {
        g_ROWSUM[i] = 0.f;
    } else if (i < 114304) {
        int j = i - MROWS;
        int z = j / 6144, rem = j % 6144;
        int r = 1000 + (rem >> 8), c = rem & 255;
        size_t off = ((size_t)z * 1024 + r) * 256 + c;
        g_ATH[off] = __ushort_as_bfloat16(0);
        g_ATL[off] = __ushort_as_bfloat16(0);
    } else if (i < 376448) {
        int idx = i - 114304;
        float v; __nv_bfloat16 *H, *L; int off;
        if (idx < 131072) {
            int n = idx >> 8, k = idx & 255;
            v = (n < 256) ? Wk[k * 256 + n] : Wv[k * 256 + (n - 256)];
            H = g_WKVTH; L = g_WKVTL; off = idx;
        } else if (idx < 196608) {
            int t = idx - 131072;
            int n = t >> 8, k = t & 255;
            v = Wq[k * 256 + n];
            H = g_WQTH; L = g_WQTL; off = t;
        } else {
            int t = idx - 196608;
            int n = t >> 8, k = t & 255;
            v = Wc[k * 256 + n];
            H = g_WCTH; L = g_WCTL; off = t;
        }
        __nv_bfloat16 h = __float2bfloat16_rn(v);
        __nv_bfloat16 l = __float2bfloat16_rn(v - __bfloat162float(h));
        H[off] = h; L[off] = l;
    } else if (i < 2473600) {
        int idx = i - 376448;
        const float* src = nodes;
        __nv_bfloat16* H = g_BH;
        __nv_bfloat16* L = g_BL;
        if (idx >= 1048576) {
            idx -= 1048576;
            src = last; H = g_LH; L = g_LL;
        }
        int c4 = idx & 63;
        int zr = idx >> 6;
        int z = zr >> 10, r = zr & 1023;
        float4 v = make_float4(0.f, 0.f, 0.f, 0.f);
        if (r < 1000)
            v = *(const float4*)(src + ((size_t)z * 1000 + r) * 256 + c4 * 4);
        float xs[4] = {v.x, v.y, v.z, v.w};
        ushort4 hh, ll;
        unsigned short* hp = &hh.x;
        unsigned short* lp = &ll.x;
#pragma unroll
        for (int j = 0; j < 4; ++j) {
            __nv_bfloat16 h = __float2bfloat16_rn(xs[j]);
            float res = xs[j] - __bfloat162float(h);
            __nv_bfloat16 l = __float2bfloat16_rn(res);
            hp[j] = __bfloat16_as_ushort(h);
            lp[j] = __bfloat16_as_ushort(l);
        }
        *(ushort4*)(H + (size_t)zr * 256 + c4 * 4) = hh;
        *(ushort4*)(L + (size_t)zr * 256 + c4 * 4) = ll;
    }
}

// ---------------- merged HMMA GEMM: K=32 double-buffer, barrier overlapped ----------------
// EPI 2: C += bias (Wc proj);  EPI 3: probe epilogue;  EPI 4: merged KV/Q projections
#define GP_PAD    40
#define GP_TILE   (128 * GP_PAD)
#define GP_OPB    (GP_TILE * 2)
#define GP_STAGE  (4 * GP_OPB)
#define G3_SMEM   (2 * GP_STAGE)

#define LDSM_SET(aAH, aAL, aBH, aBL, koff) \
    ldsm4(aH0[0], aH0[1], aH0[2], aH0[3], (aAH) + (koff)); \
    ldsm4(aH1[0], aH1[1], aH1[2], aH1[3], (aAH) + (koff) + 16 * GP_PAD * 2); \
    ldsm4(aL0[0], aL0[1], aL0[2], aL0[3], (aAL) + (koff)); \
    ldsm4(aL1[0], aL1[1], aL1[2], aL1[3], (aAL) + (koff) + 16 * GP_PAD * 2); \
    { \
        uint32_t r0, r1, r2, r3; \
        _Pragma("unroll") \
        for (int pr = 0; pr < 4; ++pr) { \
            ldsm4(r0, r1, r2, r3, (aBH) + (koff) + (uint32_t)(pr * 16 * GP_PAD * 2)); \
            bH[2*pr][0] = r0; bH[2*pr][1] = r1; \
            bH[2*pr+1][0] = r2; bH[2*pr+1][1] = r3; \
            ldsm4(r0, r1, r2, r3, (aBL) + (koff) + (uint32_t)(pr * 16 * GP_PAD * 2)); \
            bL[2*pr][0] = r0; bL[2*pr][1] = r1; \
            bL[2*pr+1][0] = r2; bL[2*pr+1][1] = r3; \
        } \
    }

#define MMA_SET() \
    _Pragma("unroll") \
    for (int ni = 0; ni < 8; ++ni) { \
        MMA16816(acc[0][ni], aH0, bH[ni][0], bH[ni][1]); \
        MMA16816(acc[1][ni], aH1, bH[ni][0], bH[ni][1]); \
    } \
    _Pragma("unroll") \
    for (int ni = 0; ni < 8; ++ni) { \
        MMA16816(acc[0][ni], aH0, bL[ni][0], bL[ni][1]); \
        MMA16816(acc[1][ni], aH1, bL[ni][0], bL[ni][1]); \
    } \
    _Pragma("unroll") \
    for (int ni = 0; ni < 8; ++ni) { \
        MMA16816(acc[0][ni], aL0, bH[ni][0], bH[ni][1]); \
        MMA16816(acc[1][ni], aL1, bH[ni][0], bH[ni][1]); \
    }

template <int EPI>
__global__ void __launch_bounds__(256, 2)
mma_gemm(const __nv_bfloat16* __restrict__ AH, const __nv_bfloat16* __restrict__ AL,
         const __nv_bfloat16* __restrict__ BH, const __nv_bfloat16* __restrict__ BL,
         __nv_bfloat16* __restrict__ CH, __nv_bfloat16* __restrict__ CL, int ldc,
         const float* __restrict__ attr, const float* __restrict__ wql,
         const float* __restrict__ bias,
         const float* __restrict__ mask, float* __restrict__ out,
         float* __restrict__ rsum)
{
    extern __shared__ __align__(16) __nv_bfloat16 smb[];

    const int tid = threadIdx.x;
    const int lane = tid & 31;
    const int w = tid >> 5;
    const int wm = w & 3, wn = w >> 2;
    const int z = blockIdx.z, m0 = blockIdx.y * 128;

    int n0;
    bool isq = false;
    const __nv_bfloat16 *pAH, *pAL, *pBH, *pBL;
    if (EPI == 4) {
        isq = (blockIdx.x >= 4);
        n0 = (isq ? (int)blockIdx.x - 4 : (int)blockIdx.x) * 128;
        if (!isq) {
            pAH = g_BH + ((size_t)z * 1024 + m0) * 256;
            pAL = g_BL + ((size_t)z * 1024 + m0) * 256;
            pBH = g_WKVTH + (size_t)n0 * 256;
            pBL = g_WKVTL + (size_t)n0 * 256;
        } else {
            pAH = g_LH + ((size_t)z * 1024 + m0) * 256;
            pAL = g_LL + ((size_t)z * 1024 + m0) * 256;
            pBH = g_WQTH + (size_t)n0 * 256;
            pBL = g_WQTL + (size_t)n0 * 256;
        }
    } else {
        n0 = blockIdx.x * 128;
        pAH = AH + ((size_t)z * 1024 + m0) * 256;
        pAL = AL + ((size_t)z * 1024 + m0) * 256;
        const size_t boff = (EPI == 3) ? ((size_t)z * 1024 + n0) * 256 : (size_t)n0 * 256;
        pBH = BH + boff;
        pBL = BL + boff;
    }

    float acc[2][8][4];
#pragma unroll
    for (int mi = 0; mi < 2; ++mi)
#pragma unroll
        for (int ni = 0; ni < 8; ++ni)
#pragma unroll
            for (int q = 0; q < 4; ++q) acc[mi][ni][q] = 0.f;

    const int arow = ((lane >> 3) & 1) * 8 + (lane & 7);
    const int acol = (lane >> 4) * 8;
    const int brow = (lane >> 4) * 8 + (lane & 7);
    const int bcol = ((lane >> 3) & 1) * 8;

    const uint32_t sA = smem_u32(smb);
    const uint32_t oAH = (uint32_t)(((wm * 32 + arow) * GP_PAD + acol) * 2);
    const uint32_t oAL = oAH + GP_OPB;
    const uint32_t oBH = 2u * GP_OPB + (uint32_t)(((wn * 64 + brow) * GP_PAD + bcol) * 2);
    const uint32_t oBL = oBH + GP_OPB;

    const int lrow = tid >> 1;
    const int lhalf = (tid & 1) * 16;
    const uint32_t sdo = (uint32_t)((lrow * GP_PAD + lhalf) * 2);
    const size_t gro = (size_t)lrow * 256;

    auto issue_chunk = [&](int kc, int buf) {
        const uint32_t st = sA + (uint32_t)buf * GP_STAGE + sdo;
        const size_t gs = gro + kc * 32 + lhalf;
#pragma unroll
        for (int half = 0; half < 2; ++half) {
            const uint32_t d = st + (uint32_t)(half * 16);
            const size_t s = gs + half * 8;
            cpa16(d,                 pAH + s);
            cpa16(d + GP_OPB,        pAL + s);
            cpa16(d + 2 * GP_OPB,    pBH + s);
            cpa16(d + 3 * GP_OPB,    pBL + s);
        }
    };

    issue_chunk(0, 0); CP_COMMIT();
    issue_chunk(1, 1); CP_COMMIT();

#pragma unroll 1
    for (int kc = 0; kc < 8; ++kc) {
        if (kc < 7) { CP_WAIT1(); } else { CP_WAIT0(); }
        __syncthreads();
        const uint32_t stb = sA + (uint32_t)(kc & 1) * GP_STAGE;
        const uint32_t aAH = stb + oAH, aAL = stb + oAL;
        const uint32_t aBH = stb + oBH, aBL = stb + oBL;

        // ks = 0: LDSM + MMA
        {
            uint32_t aH0[4], aH1[4], aL0[4], aL1[4];
            uint32_t bH[8][2], bL[8][2];
            LDSM_SET(aAH, aAL, aBH, aBL, 0u)
            MMA_SET()
        }
        // ks = 1: LDSM, then barrier + next-chunk issue overlapped with MMA tail
        {
            uint32_t aH0[4], aH1[4], aL0[4], aL1[4];
            uint32_t bH[8][2], bL[8][2];
            LDSM_SET(aAH, aAL, aBH, aBL, (uint32_t)(16 * 2))
            __syncthreads();
            if (kc + 2 <= 7) {
                issue_chunk(kc + 2, kc & 1);
                CP_COMMIT();
            }
            MMA_SET()
        }
    }

    if (EPI == 3) {
        const float* maskb = mask + (size_t)z * 1000000;
        float* outb = out + (size_t)z * 1000000;
#pragma unroll
        for (int mi = 0; mi < 2; ++mi) {
#pragma unroll
            for (int hrow = 0; hrow < 2; ++hrow) {
                int gr = m0 + wm * 32 + mi * 16 + (lane >> 2) + hrow * 8;
                bool rok = (gr < 1000);
                float rs = 0.f;
                const float* mrow = maskb + (size_t)gr * 1000;
                float* orow = outb + (size_t)gr * 1000;
#pragma unroll
                for (int ni = 0; ni < 8; ++ni) {
                    int gc = n0 + wn * 64 + ni * 8 + (lane & 3) * 2;
                    if (rok && gc < 1000) {
                        float v0 = acc[mi][ni][hrow * 2 + 0];
                        float v1 = acc[mi][ni][hrow * 2 + 1];
                        float2 m2 = *(const float2*)(mrow + gc);
                        float z0 = ex2f(v0 * (0.125f * LOG2E));
                        float z1 = ex2f(v1 * (0.125f * LOG2E));
                        float t0 = 10.f - 20.f * frcp(z0 + 1.f);
                        float t1 = 10.f - 20.f * frcp(z1 + 1.f);
                        float e0 = ex2f((t0 + m2.x) * LOG2E);
                        float e1 = ex2f((t1 + m2.y) * LOG2E);
                        *(float2*)(orow + gc) = make_float2(e0, e1);
                        rs += e0 + e1;
                    }
                }
                rs += __shfl_xor_sync(0xFFFFFFFFu, rs, 1);
                rs += __shfl_xor_sync(0xFFFFFFFFu, rs, 2);
                if ((lane & 3) == 0 && rok)
                    atomicAdd(&rsum[z * 1000 + gr], rs);
            }
        }
    } else {
        const float sc = 0.25f * LOG2E;
        __nv_bfloat16* dH;
        __nv_bfloat16* dL;
        int ldc2;
        bool doq;
        if (EPI == 4) {
            dH = isq ? g_QH : g_KVH;
            dL = isq ? g_QL : g_KVL;
            ldc2 = isq ? 256 : 512;
            doq = isq;
        } else {
            dH = CH; dL = CL; ldc2 = ldc; doq = false;
        }
#pragma unroll
        for (int mi = 0; mi < 2; ++mi) {
#pragma unroll
            for (int hrow = 0; hrow < 2; ++hrow) {
                int grow = m0 + wm * 32 + mi * 16 + (lane >> 2) + hrow * 8;
                float av = 0.f;
                if (doq && grow < 1000) av = attr[z * 1000 + grow];
#pragma unroll
                for (int ni = 0; ni < 8; ++ni) {
                    int gc = n0 + wn * 64 + ni * 8 + (lane & 3) * 2;
                    float v0 = acc[mi][ni][hrow * 2 + 0];
                    float v1 = acc[mi][ni][hrow * 2 + 1];
                    if (EPI == 4) {
                        if (doq) {
                            v0 = (v0 + av * wql[gc]) * sc;
                            v1 = (v1 + av * wql[gc + 1]) * sc;
                        }
                    }
                    if (EPI == 2) {
                        v0 += bias[gc];
                        v1 += bias[gc + 1];
                    }
                    size_t off = ((size_t)z * 1024 + grow) * ldc2 + gc;
                    split_store2(dH, dL, off, v0, v1);
                }
            }
        }
    }
}

// ---------------- HMMA flash attention (R13-proven: 32-wide tiles, 2 CTAs/SM) ----------------
#define AT_BUFSZ 36864
#define AT_SMEM  (36864 + 2 * AT_BUFSZ)

__global__ void __launch_bounds__(256, 2)
attn_mma(const float* __restrict__ mask)
{
    extern __shared__ __align__(16) char atsm[];
    const uint32_t sb = smem_u32(atsm);
    const int tid = threadIdx.x, lane = tid & 31, w = tid >> 5;
    const int p0 = blockIdx.x * 128;
    const int hg = blockIdx.y;
    const int b  = blockIdx.z;

    const __nv_bfloat16* gQHp = g_QH + ((size_t)b * 1024 + p0) * 256 + hg * 64;
    const __nv_bfloat16* gQLp = g_QL + ((size_t)b * 1024 + p0) * 256 + hg * 64;
    const float* gM = mask + (size_t)b * 1000000;

    const int kvrow = tid >> 3, kvc = tid & 7;
    const uint32_t kvdoff = (uint32_t)((kvrow * 72 + kvc * 8) * 2);

    auto issue_tile = [&](int nt, int buf) {
        const int n0 = nt * 32;
        const uint32_t base = sb + 36864u + (uint32_t)buf * AT_BUFSZ;
        size_t srow = (size_t)(b * 1024 + n0 + kvrow) * 512;
        cpa16(base + kvdoff,          g_KVH + srow + hg*64 + kvc*8);
        cpa16(base + 4608 + kvdoff,   g_KVL + srow + hg*64 + kvc*8);
        cpa16(base + 9216 + kvdoff,   g_KVH + srow + 256 + hg*64 + kvc*8);
        cpa16(base + 13824 + kvdoff,  g_KVL + srow + 256 + hg*64 + kvc*8);
#pragma unroll
        for (int i = 0; i < 4; ++i) {
            int idx = i * 256 + tid, row = idx >> 3, c = idx & 7;
            int gr = p0 + row, gc = n0 + c * 4;
            bool ok = (gr < 1000) && (gc < 1000);
            const float* src = ok ? (gM + (size_t)gr * 1000 + gc) : gM;
            cpa16p(base + 18432u + (uint32_t)((row * 36 + c * 4) * 4), src, ok ? 16 : 0);
        }
    };

#pragma unroll
    for (int i = 0; i < 4; ++i) {
        int idx = i * 256 + tid, row = idx >> 3, c = idx & 7;
        uint32_t doff = (uint32_t)((row * 72 + c * 8) * 2);
        cpa16(sb + doff,          gQHp + (size_t)row * 256 + c * 8);
        cpa16(sb + 18432 + doff,  gQLp + (size_t)row * 256 + c * 8);
    }
    issue_tile(0, 0);
    CP_COMMIT();
    issue_tile(1, 1);
    CP_COMMIT();

    const int qrow = w * 16 + (lane & 7) + ((lane >> 3) & 1) * 8;
    const int qcol = ((lane >> 4) & 1) * 8;
    const int krow = (lane & 7) + ((lane >> 4) & 1) * 8;
    const int kcol = ((lane >> 3) & 1) * 8;
    const int vrow = (lane & 7) + ((lane >> 3) & 1) * 8;
    const int vcol = ((lane >> 4) & 1) * 8;

    const uint32_t aQ = sb + (uint32_t)((qrow * 72 + qcol) * 2);

    float out[4][2][4];
    float denA[4], denB[4];
#pragma unroll
    for (int h = 0; h < 4; ++h) {
        denA[h] = 0.f; denB[h] = 0.f;
#pragma unroll
        for (int d = 0; d < 2; ++d)
#pragma unroll
            for (int q = 0; q < 4; ++q) out[h][d][q] = 0.f;
    }

#pragma unroll 1
    for (int nt = 0; nt < 32; ++nt) {
        if (nt < 31) { CP_WAIT1(); } else { CP_WAIT0(); }
        __syncthreads();

        const uint32_t bufb = sb + 36864u + (uint32_t)(nt & 1) * AT_BUFSZ;
        const uint32_t aM = bufb + 18432u;

        if (nt == 31) {
            for (int i = tid; i < 3072; i += 256) {
                int row = i / 24, c = 8 + (i - row * 24);
                asm volatile("st.shared.f32 [%0],%1;"
                             :: "r"(aM + (uint32_t)((row * 36 + c) * 4)), "f"(-1e30f));
            }
            __syncthreads();
        }

        float mk[4][4];
        {
            uint32_t ab = aM + (uint32_t)((((w * 16) + (lane >> 2)) * 36 + (lane & 3) * 2) * 4);
#pragma unroll
            for (int j = 0; j < 4; ++j) {
                asm volatile("ld.shared.v2.f32 {%0,%1},[%2];"
                             : "=f"(mk[j][0]), "=f"(mk[j][1]) : "r"(ab + (uint32_t)(j * 32)));
                asm volatile("ld.shared.v2.f32 {%0,%1},[%2];"
                             : "=f"(mk[j][2]), "=f"(mk[j][3]) : "r"(ab + (uint32_t)(j * 32 + 1152)));
            }
        }

#pragma unroll
        for (int h = 0; h < 4; ++h) {
            uint32_t qh[4], ql[4];
            ldsm4(qh[0], qh[1], qh[2], qh[3], aQ + (uint32_t)(h * 32));
            ldsm4(ql[0], ql[1], ql[2], ql[3], aQ + 18432u + (uint32_t)(h * 32));

            const uint32_t aK = bufb + (uint32_t)((krow * 72 + h * 16 + kcol) * 2);
            uint32_t kh[4][2], kl[4][2];
#pragma unroll
            for (int jj = 0; jj < 2; ++jj) {
                uint32_t r0, r1, r2, r3;
                ldsm4(r0, r1, r2, r3, aK + (uint32_t)(jj * 2304));
                kh[2*jj][0] = r0; kh[2*jj][1] = r1;
                kh[2*jj+1][0] = r2; kh[2*jj+1][1] = r3;
                ldsm4(r0, r1, r2, r3, aK + 4608u + (uint32_t)(jj * 2304));
                kl[2*jj][0] = r0; kl[2*jj][1] = r1;
                kl[2*jj+1][0] = r2; kl[2*jj+1][1] = r3;
            }
            float S[4][4];
#pragma unroll
            for (int j = 0; j < 4; ++j) {
                S[j][0] = 0.f; S[j][1] = 0.f; S[j][2] = 0.f; S[j][3] = 0.f;
                MMA16816(S[j], qh, kh[j][0], kh[j][1]);
            }
#pragma unroll
            for (int j = 0; j < 4; ++j)
                MMA16816(S[j], qh, kl[j][0], kl[j][1]);
#pragma unroll
            for (int j = 0; j < 4; ++j)
                MMA16816(S[j], ql, kh[j][0], kh[j][1]);

            uint32_t P[4][2];
            float dA = 0.f, dB = 0.f;
#pragma unroll
            for (int j = 0; j < 4; ++j) {
                float e0 = ex2f(fmaf(mk[j][0], LOG2E, S[j][0]));
                float e1 = ex2f(fmaf(mk[j][1], LOG2E, S[j][1]));
                float e2 = ex2f(fmaf(mk[j][2], LOG2E, S[j][2]));
                float e3 = ex2f(fmaf(mk[j][3], LOG2E, S[j][3]));
                dA += e0 + e1; dB += e2 + e3;
                P[j][0] = packbf(e1, e0);
                P[j][1] = packbf(e3, e2);
            }
            denA[h] += dA; denB[h] += dB;
            const uint32_t aV = bufb + 9216u + (uint32_t)((vrow * 72 + h * 16 + vcol) * 2);
#pragma unroll
            for (int kc = 0; kc < 2; ++kc) {
                uint32_t Af[4] = {P[2*kc][0], P[2*kc][1], P[2*kc+1][0], P[2*kc+1][1]};
                uint32_t v0, v1, v2, v3;
                ldsm4t(v0, v1, v2, v3, aV + (uint32_t)(kc * 2304));
                MMA16816(out[h][0], Af, v0, v1);
                MMA16816(out[h][1], Af, v2, v3);
                ldsm4t(v0, v1, v2, v3, aV + 4608u + (uint32_t)(kc * 2304));
                MMA16816(out[h][0], Af, v0, v1);
                MMA16816(out[h][1], Af, v2, v3);
            }
        }
        __syncthreads();
        if (nt + 2 <= 31) {
            issue_tile(nt + 2, nt & 1);
            CP_COMMIT();
        }
    }

    const int prA = p0 + w * 16 + (lane >> 2);
    const int prB = prA + 8;
#pragma unroll
    for (int h = 0; h < 4; ++h) {
        float dA = denA[h];
        dA += __shfl_xor_sync(0xFFFFFFFFu, dA, 1);
        dA += __shfl_xor_sync(0xFFFFFFFFu, dA, 2);
        float dB = denB[h];
        dB += __shfl_xor_sync(0xFFFFFFFFu, dB, 1);
        dB += __shfl_xor_sync(0xFFFFFFFFu, dB, 2);
        float iA = frcp(dA), iB = frcp(dB);
        int col = hg * 64 + h * 16 + (lane & 3) * 2;
        if (prA < 1000) {
            size_t off = ((size_t)b * 1024 + prA) * 256 + col;
            split_store2(g_ATH, g_ATL, off,     out[h][0][0] * iA, out[h][0][1] * iA);
            split_store2(g_ATH, g_ATL, off + 8, out[h][1][0] * iA, out[h][1][1] * iA);
        }
        if (prB < 1000) {
            size_t off = ((size_t)b * 1024 + prB) * 256 + col;
            split_store2(g_ATH, g_ATL, off,     out[h][0][2] * iB, out[h][0][3] * iB);
            split_store2(g_ATH, g_ATL, off + 8, out[h][1][2] * iB, out[h][1][3] * iB);
        }
    }
}

// ---------------- normalize ----------------
__global__ void norm_k(float* __restrict__ out) {
    int row = blockIdx.x;
    int c = threadIdx.x;
    if (c < 250) {
        float inv = 1.0f / g_ROWSUM[row];
        float4* p = (float4*)(out + (size_t)row * 1000);
        float4 v = p[c];
        v.x *= inv; v.y *= inv; v.z *= inv; v.w *= inv;
        p[c] = v;
    }
}

// ---------------- launch ----------------
extern "C" void kernel_launch(void* const* d_in, const int* in_sizes, int n_in,
                              void* d_out, int out_size)
{
    const float* last  = (const float*)d_in[0];
    const float* attr  = (const float*)d_in[1];
    const float* mask  = (const float*)d_in[2];
    const float* nodes = (const float*)d_in[3];
    const float* Wq    = (const float*)d_in[4];
    const float* Wk    = (const float*)d_in[5];
    const float* Wv    = (const float*)d_in[6];
    const float* Wc    = (const float*)d_in[7];
    const float* bc    = (const float*)d_in[8];
    float* out = (float*)d_out;

    void* p;
    cudaGetSymbolAddress(&p, g_ROWSUM); float* gRS = (float*)p;
    cudaGetSymbolAddress(&p, g_AH);     __nv_bfloat16* gAH = (__nv_bfloat16*)p;
    cudaGetSymbolAddress(&p, g_AL);     __nv_bfloat16* gAL = (__nv_bfloat16*)p;
    cudaGetSymbolAddress(&p, g_BH);     __nv_bfloat16* gBH = (__nv_bfloat16*)p;
    cudaGetSymbolAddress(&p, g_BL);     __nv_bfloat16* gBL = (__nv_bfloat16*)p;
    cudaGetSymbolAddress(&p, g_WCTH);   __nv_bfloat16* gWCTH = (__nv_bfloat16*)p;
    cudaGetSymbolAddress(&p, g_WCTL);   __nv_bfloat16* gWCTL = (__nv_bfloat16*)p;
    cudaGetSymbolAddress(&p, g_ATH);    __nv_bfloat16* gATH = (__nv_bfloat16*)p;
    cudaGetSymbolAddress(&p, g_ATL);    __nv_bfloat16* gATL = (__nv_bfloat16*)p;

    cudaFuncSetAttribute(mma_gemm<2>, cudaFuncAttributeMaxDynamicSharedMemorySize, G3_SMEM);
    cudaFuncSetAttribute(mma_gemm<3>, cudaFuncAttributeMaxDynamicSharedMemorySize, G3_SMEM);
    cudaFuncSetAttribute(mma_gemm<4>, cudaFuncAttributeMaxDynamicSharedMemorySize, G3_SMEM);
    cudaFuncSetAttribute(attn_mma, cudaFuncAttributeMaxDynamicSharedMemorySize, AT_SMEM);

    // single merged prep launch
    prep_all<<<9663, 256>>>(Wk, Wv, Wq, Wc, nodes, last);

    // merged KV + Q projections (x: 0..3 KV, 4..5 Q)
    mma_gemm<4><<<dim3(6, 8, 16), 256, G3_SMEM>>>(
        nullptr, nullptr, nullptr, nullptr, nullptr, nullptr, 0,
        attr, Wq + 256 * 256, nullptr, nullptr, nullptr, nullptr);

    attn_mma<<<dim3(8, 4, 16), 256, AT_SMEM>>>(mask);

    // Wc projection (+bias)
    mma_gemm<2><<<dim3(2, 8, 16), 256, G3_SMEM>>>(
        gATH, gATL, gWCTH, gWCTL, gAH, gAL, 256,
        nullptr, nullptr, bc, nullptr, nullptr, nullptr);

    // probe GEMM + clipped-softmax epilogue
    mma_gemm<3><<<dim3(8, 8, 16), 256, G3_SMEM>>>(
        gAH, gAL, gBH, gBL, nullptr, nullptr, 1000,
        nullptr, nullptr, nullptr, mask, out, gRS);

    norm_k<<<MROWS, 256>>>(out);
}

// round 16
// speedup vs baseline: 1.0372x; 1.0099x over previous
#include <cuda_runtime.h>
#include <cuda_bf16.h>
#include <math.h>
#include <cstdint>

// B=16, P=1000, N=1000, E=256, H=16, D=16, HD=256
#define BSZ   16
#define PN    1000
#define MROWS (BSZ * PN)
#define LOG2E 1.4426950408889634f

__device__ __forceinline__ float ex2f(float x) {
    float y; asm("ex2.approx.f32 %0,%1;" : "=f"(y) : "f"(x)); return y;
}
__device__ __forceinline__ float frcp(float x) {
    float y; asm("rcp.approx.f32 %0,%1;" : "=f"(y) : "f"(x)); return y;
}
__device__ __forceinline__ uint32_t smem_u32(const void* p) {
    uint32_t a;
    asm("{ .reg .u64 t; cvta.to.shared.u64 t, %1; cvt.u32.u64 %0, t; }"
        : "=r"(a) : "l"(p));
    return a;
}
__device__ __forceinline__ void ldsm4(uint32_t& r0, uint32_t& r1,
                                      uint32_t& r2, uint32_t& r3, uint32_t a) {
    asm volatile("ldmatrix.sync.aligned.m8n8.x4.shared.b16 {%0,%1,%2,%3},[%4];"
                 : "=r"(r0), "=r"(r1), "=r"(r2), "=r"(r3) : "r"(a));
}
__device__ __forceinline__ void ldsm4t(uint32_t& r0, uint32_t& r1,
                                       uint32_t& r2, uint32_t& r3, uint32_t a) {
    asm volatile("ldmatrix.sync.aligned.m8n8.x4.trans.shared.b16 {%0,%1,%2,%3},[%4];"
                 : "=r"(r0), "=r"(r1), "=r"(r2), "=r"(r3) : "r"(a));
}
__device__ __forceinline__ uint32_t packbf(float hi, float lo) {
    uint32_t r; asm("cvt.rn.bf16x2.f32 %0,%1,%2;" : "=r"(r) : "f"(hi), "f"(lo));
    return r;
}
__device__ __forceinline__ void cpa16(uint32_t dst, const void* src) {
    asm volatile("cp.async.cg.shared.global [%0],[%1],16;"
                 :: "r"(dst), "l"(src) : "memory");
}
__device__ __forceinline__ void cpa16p(uint32_t dst, const void* src, int n) {
    asm volatile("cp.async.cg.shared.global [%0],[%1],16,%2;"
                 :: "r"(dst), "l"(src), "r"(n) : "memory");
}
#define MMA16816(C, A, B0, B1) \
    asm volatile("mma.sync.aligned.m16n8k16.row.col.f32.bf16.bf16.f32 " \
        "{%0,%1,%2,%3},{%4,%5,%6,%7},{%8,%9},{%0,%1,%2,%3};" \
        : "+f"((C)[0]), "+f"((C)[1]), "+f"((C)[2]), "+f"((C)[3]) \
        : "r"((A)[0]), "r"((A)[1]), "r"((A)[2]), "r"((A)[3]), \
          "r"(B0), "r"(B1))
#define CP_COMMIT() asm volatile("cp.async.commit_group;" ::: "memory")
#define CP_WAIT1()  asm volatile("cp.async.wait_group 1;" ::: "memory")
#define CP_WAIT0()  asm volatile("cp.async.wait_group 0;" ::: "memory")

__device__ __forceinline__ void split_store2(__nv_bfloat16* __restrict__ H,
                                             __nv_bfloat16* __restrict__ L,
                                             size_t off, float v0, float v1) {
    __nv_bfloat16 h0 = __float2bfloat16_rn(v0);
    __nv_bfloat16 h1 = __float2bfloat16_rn(v1);
    __nv_bfloat16 l0 = __float2bfloat16_rn(v0 - __bfloat162float(h0));
    __nv_bfloat16 l1 = __float2bfloat16_rn(v1 - __bfloat162float(h1));
    ushort2 hh, ll;
    hh.x = __bfloat16_as_ushort(h0); hh.y = __bfloat16_as_ushort(h1);
    ll.x = __bfloat16_as_ushort(l0); ll.y = __bfloat16_as_ushort(l1);
    *(ushort2*)(H + off) = hh;
    *(ushort2*)(L + off) = ll;
}

// ---------------- scratch ----------------
__device__ float g_ROWSUM[MROWS];
__device__ __nv_bfloat16 g_AH[16 * 1024 * 256];
__device__ __nv_bfloat16 g_AL[16 * 1024 * 256];
__device__ __nv_bfloat16 g_BH[16 * 1024 * 256];
__device__ __nv_bfloat16 g_BL[16 * 1024 * 256];
__device__ __nv_bfloat16 g_QH[16 * 1024 * 256];
__device__ __nv_bfloat16 g_QL[16 * 1024 * 256];
__device__ __nv_bfloat16 g_KVH[16 * 1024 * 512];
__device__ __nv_bfloat16 g_KVL[16 * 1024 * 512];
__device__ __nv_bfloat16 g_LH[16 * 1024 * 256];
__device__ __nv_bfloat16 g_LL[16 * 1024 * 256];
__device__ __nv_bfloat16 g_ATH[16 * 1024 * 256];
__device__ __nv_bfloat16 g_ATL[16 * 1024 * 256];
__device__ __nv_bfloat16 g_WKVTH[512 * 256];
__device__ __nv_bfloat16 g_WKVTL[512 * 256];
__device__ __nv_bfloat16 g_WQTH[256 * 256];
__device__ __nv_bfloat16 g_WQTL[256 * 256];
__device__ __nv_bfloat16 g_WCTH[256 * 256];
__device__ __nv_bfloat16 g_WCTL[256 * 256];

// ---------------- single merged prep kernel ----------------
__global__ void prep_all(const float* __restrict__ Wk, const float* __restrict__ Wv,
                         const float* __restrict__ Wq, const float* __restrict__ Wc,
                         const float* __restrict__ nodes, const float* __restrict__ last)
{
    int i = blockIdx.x * 256 + threadIdx.x;
    if (i < MROWS) {
        g_ROWSUM[i] = 0.f;
    } else if (i < 114304) {
        int j = i - MROWS;
        int z = j / 6144, rem = j % 6144;
        int r = 1000 + (rem >> 8), c = rem & 255;
        size_t off = ((size_t)z * 1024 + r) * 256 + c;
        g_ATH[off] = __ushort_as_bfloat16(0);
        g_ATL[off] = __ushort_as_bfloat16(0);
    } else if (i < 376448) {
        int idx = i - 114304;
        float v; __nv_bfloat16 *H, *L; int off;
        if (idx < 131072) {
            int n = idx >> 8, k = idx & 255;
            v = (n < 256) ? Wk[k * 256 + n] : Wv[k * 256 + (n - 256)];
            H = g_WKVTH; L = g_WKVTL; off = idx;
        } else if (idx < 196608) {
            int t = idx - 131072;
            int n = t >> 8, k = t & 255;
            v = Wq[k * 256 + n];
            H = g_WQTH; L = g_WQTL; off = t;
        } else {
            int t = idx - 196608;
            int n = t >> 8, k = t & 255;
            v = Wc[k * 256 + n];
            H = g_WCTH; L = g_WCTL; off = t;
        }
        __nv_bfloat16 h = __float2bfloat16_rn(v);
        __nv_bfloat16 l = __float2bfloat16_rn(v - __bfloat162float(h));
        H[off] = h; L[off] = l;
    } else if (i < 2473600) {
        int idx = i - 376448;
        const float* src = nodes;
        __nv_bfloat16* H = g_BH;
        __nv_bfloat16* L = g_BL;
        if (idx >= 1048576) {
            idx -= 1048576;
            src = last; H = g_LH; L = g_LL;
        }
        int c4 = idx & 63;
        int zr = idx >> 6;
        int z = zr >> 10, r = zr & 1023;
        float4 v = make_float4(0.f, 0.f, 0.f, 0.f);
        if (r < 1000)
            v = *(const float4*)(src + ((size_t)z * 1000 + r) * 256 + c4 * 4);
        float xs[4] = {v.x, v.y, v.z, v.w};
        ushort4 hh, ll;
        unsigned short* hp = &hh.x;
        unsigned short* lp = &ll.x;
#pragma unroll
        for (int j = 0; j < 4; ++j) {
            __nv_bfloat16 h = __float2bfloat16_rn(xs[j]);
            float res = xs[j] - __bfloat162float(h);
            __nv_bfloat16 l = __float2bfloat16_rn(res);
            hp[j] = __bfloat16_as_ushort(h);
            lp[j] = __bfloat16_as_ushort(l);
        }
        *(ushort4*)(H + (size_t)zr * 256 + c4 * 4) = hh;
        *(ushort4*)(L + (size_t)zr * 256 + c4 * 4) = ll;
    }
}

// ---------------- merged HMMA GEMM (R14-proven) ----------------
#define GP_PAD    40
#define GP_TILE   (128 * GP_PAD)
#define GP_OPB    (GP_TILE * 2)
#define GP_STAGE  (4 * GP_OPB)
#define G3_SMEM   (2 * GP_STAGE)

#define LDSM_SET(aAH, aAL, aBH, aBL, koff) \
    ldsm4(aH0[0], aH0[1], aH0[2], aH0[3], (aAH) + (koff)); \
    ldsm4(aH1[0], aH1[1], aH1[2], aH1[3], (aAH) + (koff) + 16 * GP_PAD * 2); \
    ldsm4(aL0[0], aL0[1], aL0[2], aL0[3], (aAL) + (koff)); \
    ldsm4(aL1[0], aL1[1], aL1[2], aL1[3], (aAL) + (koff) + 16 * GP_PAD * 2); \
    { \
        uint32_t r0, r1, r2, r3; \
        _Pragma("unroll") \
        for (int pr = 0; pr < 4; ++pr) { \
            ldsm4(r0, r1, r2, r3, (aBH) + (koff) + (uint32_t)(pr * 16 * GP_PAD * 2)); \
            bH[2*pr][0] = r0; bH[2*pr][1] = r1; \
            bH[2*pr+1][0] = r2; bH[2*pr+1][1] = r3; \
            ldsm4(r0, r1, r2, r3, (aBL) + (koff) + (uint32_t)(pr * 16 * GP_PAD * 2)); \
            bL[2*pr][0] = r0; bL[2*pr][1] = r1; \
            bL[2*pr+1][0] = r2; bL[2*pr+1][1] = r3; \
        } \
    }

#define MMA_SET() \
    _Pragma("unroll") \
    for (int ni = 0; ni < 8; ++ni) { \
        MMA16816(acc[0][ni], aH0, bH[ni][0], bH[ni][1]); \
        MMA16816(acc[1][ni], aH1, bH[ni][0], bH[ni][1]); \
    } \
    _Pragma("unroll") \
    for (int ni = 0; ni < 8; ++ni) { \
        MMA16816(acc[0][ni], aH0, bL[ni][0], bL[ni][1]); \
        MMA16816(acc[1][ni], aH1, bL[ni][0], bL[ni][1]); \
    } \
    _Pragma("unroll") \
    for (int ni = 0; ni < 8; ++ni) { \
        MMA16816(acc[0][ni], aL0, bH[ni][0], bH[ni][1]); \
        MMA16816(acc[1][ni], aL1, bH[ni][0], bH[ni][1]); \
    }

template <int EPI>
__global__ void __launch_bounds__(256, 2)
mma_gemm(const __nv_bfloat16* __restrict__ AH, const __nv_bfloat16* __restrict__ AL,
         const __nv_bfloat16* __restrict__ BH, const __nv_bfloat16* __restrict__ BL,
         __nv_bfloat16* __restrict__ CH, __nv_bfloat16* __restrict__ CL, int ldc,
         const float* __restrict__ attr, const float* __restrict__ wql,
         const float* __restrict__ bias,
         const float* __restrict__ mask, float* __restrict__ out,
         float* __restrict__ rsum)
{
    extern __shared__ __align__(16) __nv_bfloat16 smb[];

    const int tid = threadIdx.x;
    const int lane = tid & 31;
    const int w = tid >> 5;
    const int wm = w & 3, wn = w >> 2;
    const int z = blockIdx.z, m0 = blockIdx.y * 128;

    int n0;
    bool isq = false;
    const __nv_bfloat16 *pAH, *pAL, *pBH, *pBL;
    if (EPI == 4) {
        isq = (blockIdx.x >= 4);
        n0 = (isq ? (int)blockIdx.x - 4 : (int)blockIdx.x) * 128;
        if (!isq) {
            pAH = g_BH + ((size_t)z * 1024 + m0) * 256;
            pAL = g_BL + ((size_t)z * 1024 + m0) * 256;
            pBH = g_WKVTH + (size_t)n0 * 256;
            pBL = g_WKVTL + (size_t)n0 * 256;
        } else {
            pAH = g_LH + ((size_t)z * 1024 + m0) * 256;
            pAL = g_LL + ((size_t)z * 1024 + m0) * 256;
            pBH = g_WQTH + (size_t)n0 * 256;
            pBL = g_WQTL + (size_t)n0 * 256;
        }
    } else {
        n0 = blockIdx.x * 128;
        pAH = AH + ((size_t)z * 1024 + m0) * 256;
        pAL = AL + ((size_t)z * 1024 + m0) * 256;
        const size_t boff = (EPI == 3) ? ((size_t)z * 1024 + n0) * 256 : (size_t)n0 * 256;
        pBH = BH + boff;
        pBL = BL + boff;
    }

    float acc[2][8][4];
#pragma unroll
    for (int mi = 0; mi < 2; ++mi)
#pragma unroll
        for (int ni = 0; ni < 8; ++ni)
#pragma unroll
            for (int q = 0; q < 4; ++q) acc[mi][ni][q] = 0.f;

    const int arow = ((lane >> 3) & 1) * 8 + (lane & 7);
    const int acol = (lane >> 4) * 8;
    const int brow = (lane >> 4) * 8 + (lane & 7);
    const int bcol = ((lane >> 3) & 1) * 8;

    const uint32_t sA = smem_u32(smb);
    const uint32_t oAH = (uint32_t)(((wm * 32 + arow) * GP_PAD + acol) * 2);
    const uint32_t oAL = oAH + GP_OPB;
    const uint32_t oBH = 2u * GP_OPB + (uint32_t)(((wn * 64 + brow) * GP_PAD + bcol) * 2);
    const uint32_t oBL = oBH + GP_OPB;

    const int lrow = tid >> 1;
    const int lhalf = (tid & 1) * 16;
    const uint32_t sdo = (uint32_t)((lrow * GP_PAD + lhalf) * 2);
    const size_t gro = (size_t)lrow * 256;

    auto issue_chunk = [&](int kc, int buf) {
        const uint32_t st = sA + (uint32_t)buf * GP_STAGE + sdo;
        const size_t gs = gro + kc * 32 + lhalf;
#pragma unroll
        for (int half = 0; half < 2; ++half) {
            const uint32_t d = st + (uint32_t)(half * 16);
            const size_t s = gs + half * 8;
            cpa16(d,                 pAH + s);
            cpa16(d + GP_OPB,        pAL + s);
            cpa16(d + 2 * GP_OPB,    pBH + s);
            cpa16(d + 3 * GP_OPB,    pBL + s);
        }
    };

    issue_chunk(0, 0); CP_COMMIT();
    issue_chunk(1, 1); CP_COMMIT();

#pragma unroll 1
    for (int kc = 0; kc < 8; ++kc) {
        if (kc < 7) { CP_WAIT1(); } else { CP_WAIT0(); }
        __syncthreads();
        const uint32_t stb = sA + (uint32_t)(kc & 1) * GP_STAGE;
        const uint32_t aAH = stb + oAH, aAL = stb + oAL;
        const uint32_t aBH = stb + oBH, aBL = stb + oBL;

        {
            uint32_t aH0[4], aH1[4], aL0[4], aL1[4];
            uint32_t bH[8][2], bL[8][2];
            LDSM_SET(aAH, aAL, aBH, aBL, 0u)
            MMA_SET()
        }
        {
            uint32_t aH0[4], aH1[4], aL0[4], aL1[4];
            uint32_t bH[8][2], bL[8][2];
            LDSM_SET(aAH, aAL, aBH, aBL, (uint32_t)(16 * 2))
            __syncthreads();
            if (kc + 2 <= 7) {
                issue_chunk(kc + 2, kc & 1);
                CP_COMMIT();
            }
            MMA_SET()
        }
    }

    if (EPI == 3) {
        const float* maskb = mask + (size_t)z * 1000000;
        float* outb = out + (size_t)z * 1000000;
#pragma unroll
        for (int mi = 0; mi < 2; ++mi) {
#pragma unroll
            for (int hrow = 0; hrow < 2; ++hrow) {
                int gr = m0 + wm * 32 + mi * 16 + (lane >> 2) + hrow * 8;
                bool rok = (gr < 1000);
                float rs = 0.f;
                const float* mrow = maskb + (size_t)gr * 1000;
                float* orow = outb + (size_t)gr * 1000;
#pragma unroll
                for (int ni = 0; ni < 8; ++ni) {
                    int gc = n0 + wn * 64 + ni * 8 + (lane & 3) * 2;
                    if (rok && gc < 1000) {
                        float v0 = acc[mi][ni][hrow * 2 + 0];
                        float v1 = acc[mi][ni][hrow * 2 + 1];
                        float2 m2 = *(const float2*)(mrow + gc);
                        float z0 = ex2f(v0 * (0.125f * LOG2E));
                        float z1 = ex2f(v1 * (0.125f * LOG2E));
                        float t0 = 10.f - 20.f * frcp(z0 + 1.f);
                        float t1 = 10.f - 20.f * frcp(z1 + 1.f);
                        float e0 = ex2f((t0 + m2.x) * LOG2E);
                        float e1 = ex2f((t1 + m2.y) * LOG2E);
                        *(float2*)(orow + gc) = make_float2(e0, e1);
                        rs += e0 + e1;
                    }
                }
                rs += __shfl_xor_sync(0xFFFFFFFFu, rs, 1);
                rs += __shfl_xor_sync(0xFFFFFFFFu, rs, 2);
                if ((lane & 3) == 0 && rok)
                    atomicAdd(&rsum[z * 1000 + gr], rs);
            }
        }
    } else {
        const float sc = 0.25f * LOG2E;
        __nv_bfloat16* dH;
        __nv_bfloat16* dL;
        int ldc2;
        bool doq;
        if (EPI == 4) {
            dH = isq ? g_QH : g_KVH;
            dL = isq ? g_QL : g_KVL;
            ldc2 = isq ? 256 : 512;
            doq = isq;
        } else {
            dH = CH; dL = CL; ldc2 = ldc; doq = false;
        }
#pragma unroll
        for (int mi = 0; mi < 2; ++mi) {
#pragma unroll
            for (int hrow = 0; hrow < 2; ++hrow) {
                int grow = m0 + wm * 32 + mi * 16 + (lane >> 2) + hrow * 8;
                float av = 0.f;
                if (doq && grow < 1000) av = attr[z * 1000 + grow];
#pragma unroll
                for (int ni = 0; ni < 8; ++ni) {
                    int gc = n0 + wn * 64 + ni * 8 + (lane & 3) * 2;
                    float v0 = acc[mi][ni][hrow * 2 + 0];
                    float v1 = acc[mi][ni][hrow * 2 + 1];
                    if (EPI == 4) {
                        if (doq) {
                            v0 = (v0 + av * wql[gc]) * sc;
                            v1 = (v1 + av * wql[gc + 1]) * sc;
                        }
                    }
                    if (EPI == 2) {
                        v0 += bias[gc];
                        v1 += bias[gc + 1];
                    }
                    size_t off = ((size_t)z * 1024 + grow) * ldc2 + gc;
                    split_store2(dH, dL, off, v0, v1);
                }
            }
        }
    }
}

// ---------------- HMMA flash attention: 3-buffer rotation, Q in regs (race fixed) ----------------
// buffers (36864 B each): KH@0 KL@4608 VH@9216 VL@13824 ([32][72] bf16), mask@18432 ([128][36] f32)
// tile nt lives in buffer (nt+1)%3; buffer 0 region initially holds QH@0 / QL@18432
#define AT_BUFSZ 36864
#define AT_SMEM  (3 * AT_BUFSZ)   // 110592

__global__ void __launch_bounds__(256, 2)
attn_mma(const float* __restrict__ mask)
{
    extern __shared__ __align__(16) char atsm[];
    const uint32_t sb = smem_u32(atsm);
    const int tid = threadIdx.x, lane = tid & 31, w = tid >> 5;
    const int p0 = blockIdx.x * 128;
    const int hg = blockIdx.y;
    const int b  = blockIdx.z;

    const __nv_bfloat16* gQHp = g_QH + ((size_t)b * 1024 + p0) * 256 + hg * 64;
    const __nv_bfloat16* gQLp = g_QL + ((size_t)b * 1024 + p0) * 256 + hg * 64;
    const float* gM = mask + (size_t)b * 1000000;

    const int kvrow = tid >> 3, kvc = tid & 7;
    const uint32_t kvdoff = (uint32_t)((kvrow * 72 + kvc * 8) * 2);

    auto issue_tile = [&](int nt) {
        const int n0 = nt * 32;
        const uint32_t base = sb + (uint32_t)((nt + 1) % 3) * AT_BUFSZ;
        size_t srow = (size_t)(b * 1024 + n0 + kvrow) * 512;
        cpa16(base + kvdoff,          g_KVH + srow + hg*64 + kvc*8);
        cpa16(base + 4608 + kvdoff,   g_KVL + srow + hg*64 + kvc*8);
        cpa16(base + 9216 + kvdoff,   g_KVH + srow + 256 + hg*64 + kvc*8);
        cpa16(base + 13824 + kvdoff,  g_KVL + srow + 256 + hg*64 + kvc*8);
#pragma unroll
        for (int i = 0; i < 4; ++i) {
            int idx = i * 256 + tid, row = idx >> 3, c = idx & 7;
            int gr = p0 + row, gc = n0 + c * 4;
            bool ok = (gr < 1000) && (gc < 1000);
            const float* src = ok ? (gM + (size_t)gr * 1000 + gc) : gM;
            cpa16p(base + 18432u + (uint32_t)((row * 36 + c * 4) * 4), src, ok ? 16 : 0);
        }
    };

    // prologue: Q into buffer-0 region + tile0 (group A), tile1 (group B)
#pragma unroll
    for (int i = 0; i < 4; ++i) {
        int idx = i * 256 + tid, row = idx >> 3, c = idx & 7;
        uint32_t doff = (uint32_t)((row * 72 + c * 8) * 2);
        cpa16(sb + doff,          gQHp + (size_t)row * 256 + c * 8);
        cpa16(sb + 18432 + doff,  gQLp + (size_t)row * 256 + c * 8);
    }
    issue_tile(0);
    CP_COMMIT();
    issue_tile(1);
    CP_COMMIT();

    const int qrow = w * 16 + (lane & 7) + ((lane >> 3) & 1) * 8;
    const int qcol = ((lane >> 4) & 1) * 8;
    const int krow = (lane & 7) + ((lane >> 4) & 1) * 8;
    const int kcol = ((lane >> 3) & 1) * 8;
    const int vrow = (lane & 7) + ((lane >> 3) & 1) * 8;
    const int vcol = ((lane >> 4) & 1) * 8;

    uint32_t qh[4][4], ql[4][4];
    float out[4][2][4];
    float denA[4], denB[4];
#pragma unroll
    for (int h = 0; h < 4; ++h) {
        denA[h] = 0.f; denB[h] = 0.f;
#pragma unroll
        for (int d = 0; d < 2; ++d)
#pragma unroll
            for (int q = 0; q < 4; ++q) out[h][d][q] = 0.f;
    }

#pragma unroll 1
    for (int nt = 0; nt < 32; ++nt) {
        if (nt < 31) { CP_WAIT1(); } else { CP_WAIT0(); }
        __syncthreads();   // all group data visible; prior-tile reads done

        if (nt == 0) {
            // Q now visible to all threads; read, then barrier before recycling its region
            const uint32_t aQ = sb + (uint32_t)((qrow * 72 + qcol) * 2);
#pragma unroll
            for (int h = 0; h < 4; ++h) {
                ldsm4(qh[h][0], qh[h][1], qh[h][2], qh[h][3], aQ + (uint32_t)(h * 32));
                ldsm4(ql[h][0], ql[h][1], ql[h][2], ql[h][3], aQ + 18432u + (uint32_t)(h * 32));
            }
            __syncthreads();   // all warps have consumed Q; buffer 0 may be overwritten
        }
        if (nt + 2 <= 31) {
            issue_tile(nt + 2);   // targets buffer nt%3, free after the barrier(s)
            CP_COMMIT();
        }

        const uint32_t bufb = sb + (uint32_t)((nt + 1) % 3) * AT_BUFSZ;
        const uint32_t aM = bufb + 18432u;

        if (nt == 31) {
            for (int i = tid; i < 3072; i += 256) {
                int row = i / 24, c = 8 + (i - row * 24);
                asm volatile("st.shared.f32 [%0],%1;"
                             :: "r"(aM + (uint32_t)((row * 36 + c) * 4)), "f"(-1e30f));
            }
            __syncthreads();
        }

        float mk[4][4];
        {
            uint32_t ab = aM + (uint32_t)((((w * 16) + (lane >> 2)) * 36 + (lane & 3) * 2) * 4);
#pragma unroll
            for (int j = 0; j < 4; ++j) {
                asm volatile("ld.shared.v2.f32 {%0,%1},[%2];"
                             : "=f"(mk[j][0]), "=f"(mk[j][1]) : "r"(ab + (uint32_t)(j * 32)));
                asm volatile("ld.shared.v2.f32 {%0,%1},[%2];"
                             : "=f"(mk[j][2]), "=f"(mk[j][3]) : "r"(ab + (uint32_t)(j * 32 + 1152)));
            }
        }

#pragma unroll
        for (int h = 0; h < 4; ++h) {
            const uint32_t aK = bufb + (uint32_t)((krow * 72 + h * 16 + kcol) * 2);
            float S[4][4];
            {
                uint32_t kf[4][2];
#pragma unroll
                for (int jj = 0; jj < 2; ++jj) {
                    uint32_t r0, r1, r2, r3;
                    ldsm4(r0, r1, r2, r3, aK + (uint32_t)(jj * 2304));
                    kf[2*jj][0] = r0; kf[2*jj][1] = r1;
                    kf[2*jj+1][0] = r2; kf[2*jj+1][1] = r3;
                }
#pragma unroll
                for (int j = 0; j < 4; ++j) {
                    S[j][0] = 0.f; S[j][1] = 0.f; S[j][2] = 0.f; S[j][3] = 0.f;
                    MMA16816(S[j], qh[h], kf[j][0], kf[j][1]);
                }
#pragma unroll
                for (int j = 0; j < 4; ++j)
                    MMA16816(S[j], ql[h], kf[j][0], kf[j][1]);
#pragma unroll
                for (int jj = 0; jj < 2; ++jj) {
                    uint32_t r0, r1, r2, r3;
                    ldsm4(r0, r1, r2, r3, aK + 4608u + (uint32_t)(jj * 2304));
                    kf[2*jj][0] = r0; kf[2*jj][1] = r1;
                    kf[2*jj+1][0] = r2; kf[2*jj+1][1] = r3;
                }
#pragma unroll
                for (int j = 0; j < 4; ++j)
                    MMA16816(S[j], qh[h], kf[j][0], kf[j][1]);
            }

            uint32_t P[4][2];
            float dA = 0.f, dB = 0.f;
#pragma unroll
            for (int j = 0; j < 4; ++j) {
                float e0 = ex2f(fmaf(mk[j][0], LOG2E, S[j][0]));
                float e1 = ex2f(fmaf(mk[j][1], LOG2E, S[j][1]));
                float e2 = ex2f(fmaf(mk[j][2], LOG2E, S[j][2]));
                float e3 = ex2f(fmaf(mk[j][3], LOG2E, S[j][3]));
                dA += e0 + e1; dB += e2 + e3;
                P[j][0] = packbf(e1, e0);
                P[j][1] = packbf(e3, e2);
            }
            denA[h] += dA; denB[h] += dB;
            const uint32_t aV = bufb + 9216u + (uint32_t)((vrow * 72 + h * 16 + vcol) * 2);
#pragma unroll
            for (int kc = 0; kc < 2; ++kc) {
                uint32_t Af[4] = {P[2*kc][0], P[2*kc][1], P[2*kc+1][0], P[2*kc+1][1]};
                uint32_t v0, v1, v2, v3;
                ldsm4t(v0, v1, v2, v3, aV + (uint32_t)(kc * 2304));
                MMA16816(out[h][0], Af, v0, v1);
                MMA16816(out[h][1], Af, v2, v3);
                ldsm4t(v0, v1, v2, v3, aV + 4608u + (uint32_t)(kc * 2304));
                MMA16816(out[h][0], Af, v0, v1);
                MMA16816(out[h][1], Af, v2, v3);
            }
        }
        // next iteration's top barrier guards buffer reuse
    }

    const int prA = p0 + w * 16 + (lane >> 2);
    const int prB = prA + 8;
#pragma unroll
    for (int h = 0; h < 4; ++h) {
        float dA = denA[h];
        dA += __shfl_xor_sync(0xFFFFFFFFu, dA, 1);
        dA += __shfl_xor_sync(0xFFFFFFFFu, dA, 2);
        float dB = denB[h];
        dB += __shfl_xor_sync(0xFFFFFFFFu, dB, 1);
        dB += __shfl_xor_sync(0xFFFFFFFFu, dB, 2);
        float iA = frcp(dA), iB = frcp(dB);
        int col = hg * 64 + h * 16 + (lane & 3) * 2;
        if (prA < 1000) {
            size_t off = ((size_t)b * 1024 + prA) * 256 + col;
            split_store2(g_ATH, g_ATL, off,     out[h][0][0] * iA, out[h][0][1] * iA);
            split_store2(g_ATH, g_ATL, off + 8, out[h][1][0] * iA, out[h][1][1] * iA);
        }
        if (prB < 1000) {
            size_t off = ((size_t)b * 1024 + prB) * 256 + col;
            split_store2(g_ATH, g_ATL, off,     out[h][0][2] * iB, out[h][0][3] * iB);
            split_store2(g_ATH, g_ATL, off + 8, out[h][1][2] * iB, out[h][1][3] * iB);
        }
    }
}

// ---------------- normalize: 8 rows per CTA (one warp per row) ----------------
__global__ void norm_k(float* __restrict__ out) {
    int row = blockIdx.x * 8 + (threadIdx.x >> 5);
    int lane = threadIdx.x & 31;
    if (row < MROWS) {
        float inv = 1.0f / g_ROWSUM[row];
        float4* p = (float4*)(out + (size_t)row * 1000);
#pragma unroll
        for (int c = lane; c < 250; c += 32) {
            float4 v = p[c];
            v.x *= inv; v.y *= inv; v.z *= inv; v.w *= inv;
            p[c] = v;
        }
    }
}

// ---------------- launch ----------------
extern "C" void kernel_launch(void* const* d_in, const int* in_sizes, int n_in,
                              void* d_out, int out_size)
{
    const float* last  = (const float*)d_in[0];
    const float* attr  = (const float*)d_in[1];
    const float* mask  = (const float*)d_in[2];
    const float* nodes = (const float*)d_in[3];
    const float* Wq    = (const float*)d_in[4];
    const float* Wk    = (const float*)d_in[5];
    const float* Wv    = (const float*)d_in[6];
    const float* Wc    = (const float*)d_in[7];
    const float* bc    = (const float*)d_in[8];
    float* out = (float*)d_out;

    void* p;
    cudaGetSymbolAddress(&p, g_ROWSUM); float* gRS = (float*)p;
    cudaGetSymbolAddress(&p, g_AH);     __nv_bfloat16* gAH = (__nv_bfloat16*)p;
    cudaGetSymbolAddress(&p, g_AL);     __nv_bfloat16* gAL = (__nv_bfloat16*)p;
    cudaGetSymbolAddress(&p, g_BH);     __nv_bfloat16* gBH = (__nv_bfloat16*)p;
    cudaGetSymbolAddress(&p, g_BL);     __nv_bfloat16* gBL = (__nv_bfloat16*)p;
    cudaGetSymbolAddress(&p, g_WCTH);   __nv_bfloat16* gWCTH = (__nv_bfloat16*)p;
    cudaGetSymbolAddress(&p, g_WCTL);   __nv_bfloat16* gWCTL = (__nv_bfloat16*)p;
    cudaGetSymbolAddress(&p, g_ATH);    __nv_bfloat16* gATH = (__nv_bfloat16*)p;
    cudaGetSymbolAddress(&p, g_ATL);    __nv_bfloat16* gATL = (__nv_bfloat16*)p;

    cudaFuncSetAttribute(mma_gemm<2>, cudaFuncAttributeMaxDynamicSharedMemorySize, G3_SMEM);
    cudaFuncSetAttribute(mma_gemm<3>, cudaFuncAttributeMaxDynamicSharedMemorySize, G3_SMEM);
    cudaFuncSetAttribute(mma_gemm<4>, cudaFuncAttributeMaxDynamicSharedMemorySize, G3_SMEM);
    cudaFuncSetAttribute(attn_mma, cudaFuncAttributeMaxDynamicSharedMemorySize, AT_SMEM);

    prep_all<<<9663, 256>>>(Wk, Wv, Wq, Wc, nodes, last);

    mma_gemm<4><<<dim3(6, 8, 16), 256, G3_SMEM>>>(
        nullptr, nullptr, nullptr, nullptr, nullptr, nullptr, 0,
        attr, Wq + 256 * 256, nullptr, nullptr, nullptr, nullptr);

    attn_mma<<<dim3(8, 4, 16), 256, AT_SMEM>>>(mask);

    mma_gemm<2><<<dim3(2, 8, 16), 256, G3_SMEM>>>(
        gATH, gATL, gWCTH, gWCTL, gAH, gAL, 256,
        nullptr, nullptr, bc, nullptr, nullptr, nullptr);

    mma_gemm<3><<<dim3(8, 8, 16), 256, G3_SMEM>>>(
        gAH, gAL, gBH, gBL, nullptr, nullptr, 1000,
        nullptr, nullptr, nullptr, mask, out, gRS);

    norm_k<<<2000, 256>>>(out);
}